// round 9
// baseline (speedup 1.0000x reference)
#include <cuda_runtime.h>
#include <cuda_bf16.h>
#include <cuda_fp16.h>
#include <cstdint>

#define FIN     128
#define NNODES  100000
#define NEDGE   1600000
#define ETOTMAX (NEDGE + NNODES)

#define BM 128
#define BN 128
#define BK 32
#define BKP 40            // padded SMEM row length (bf16 elems) = 80 bytes
#define STG_BYTES 40960   // per double-buffer stage (A hi/lo + B hi/lo)
#define SM_GEMM (2 * STG_BYTES)

// ---------------- scratch (static device globals; no runtime allocation) ----
__device__ __half g_xh[(size_t)NNODES * 256];         // GEMM output (fp16)
__device__ __nv_bfloat16 g_ahi[(size_t)NNODES * 256]; // A split hi (GEMM input)
__device__ __nv_bfloat16 g_alo[(size_t)NNODES * 256]; // A split lo
__device__ float g_als[NNODES * 8];
__device__ float g_ald[NNODES * 8];
__device__ int   g_src[ETOTMAX];
__device__ int   g_dst[ETOTMAX];
__device__ int   g_deg[NNODES + 1];
__device__ int   g_rp[NNODES + 1];
__device__ int   g_cur[NNODES];
__device__ int   g_csrc[ETOTMAX];
__device__ int   g_bs[256];
__device__ int   g_is64;
__device__ __nv_bfloat16 g_wthi[3][256 * 256];        // per-layer weight hi
__device__ __nv_bfloat16 g_wtlo[3][256 * 256];        // per-layer weight lo

// ======================= small PTX helpers ==================================
__device__ __forceinline__ uint32_t smem_to_u32(const void* p) {
    uint32_t a;
    asm("{ .reg .u64 t; cvta.to.shared.u64 t, %1; cvt.u32.u64 %0, t; }"
        : "=r"(a) : "l"(p));
    return a;
}
__device__ __forceinline__ void ldsm4(uint32_t* r, uint32_t addr) {
    asm volatile("ldmatrix.sync.aligned.m8n8.x4.shared.b16 {%0,%1,%2,%3}, [%4];"
                 : "=r"(r[0]), "=r"(r[1]), "=r"(r[2]), "=r"(r[3]) : "r"(addr));
}
__device__ __forceinline__ void mma_bf16(float* c, const uint32_t* a, const uint32_t* b) {
    asm volatile("mma.sync.aligned.m16n8k16.row.col.f32.bf16.bf16.f32 "
                 "{%0,%1,%2,%3}, {%4,%5,%6,%7}, {%8,%9}, {%0,%1,%2,%3};"
                 : "+f"(c[0]), "+f"(c[1]), "+f"(c[2]), "+f"(c[3])
                 : "r"(a[0]), "r"(a[1]), "r"(a[2]), "r"(a[3]), "r"(b[0]), "r"(b[1]));
}
__device__ __forceinline__ uint32_t pack_bf16(float a, float b) {
    __nv_bfloat162 t;
    t.x = __float2bfloat16_rn(a);
    t.y = __float2bfloat16_rn(b);
    return *reinterpret_cast<uint32_t*>(&t);
}

// ------- detect edge dtype (block 0) + zero degree array (all blocks) -------
__global__ void detect_zero_k(const unsigned int* __restrict__ w,
                              int* __restrict__ deg, int n) {
    if (blockIdx.x == 0) {
        __shared__ int flag;
        if (threadIdx.x == 0) flag = 0;
        __syncthreads();
        int local = 0;
        for (int i = threadIdx.x; i < 2048; i += blockDim.x)
            if ((i & 1) && w[i]) local = 1;
        if (local) atomicOr(&flag, 1);
        __syncthreads();
        if (threadIdx.x == 0) g_is64 = flag ? 0 : 1;
    }
    for (int i = blockIdx.x * blockDim.x + threadIdx.x; i < n;
         i += gridDim.x * blockDim.x)
        deg[i] = 0;
}

__global__ void decode_count_k(const void* __restrict__ ei, int ne, int n) {
    int e = blockIdx.x * blockDim.x + threadIdx.x;
    int et = ne + n;
    if (e >= et) return;
    int s, d;
    if (e < ne) {
        if (g_is64) {
            const long long* p = (const long long*)ei;
            s = (int)p[e];
            d = (int)p[(size_t)ne + e];
        } else {
            const int* p = (const int*)ei;
            s = p[e];
            d = p[ne + e];
        }
    } else {
        s = e - ne; d = e - ne;
    }
    g_src[e] = s;
    g_dst[e] = d;
    atomicAdd(&g_deg[d], 1);
}

// ---------------- CSR build --------------------------------------------------
__global__ void scan1_k(const int* __restrict__ deg, int* __restrict__ ex,
                        int* __restrict__ bsums, int n) {
    __shared__ int sh[1024];
    int i = blockIdx.x * 1024 + threadIdx.x;
    int v = (i < n) ? deg[i] : 0;
    sh[threadIdx.x] = v;
    __syncthreads();
    for (int off = 1; off < 1024; off <<= 1) {
        int t = (threadIdx.x >= off) ? sh[threadIdx.x - off] : 0;
        __syncthreads();
        sh[threadIdx.x] += t;
        __syncthreads();
    }
    if (i < n) ex[i] = sh[threadIdx.x] - v;
    if (threadIdx.x == 1023) bsums[blockIdx.x] = sh[1023];
}
__global__ void scan2_k(int* __restrict__ bsums, int nb) {
    __shared__ int sh[256];
    int v = (threadIdx.x < nb) ? bsums[threadIdx.x] : 0;
    sh[threadIdx.x] = v;
    __syncthreads();
    for (int off = 1; off < 256; off <<= 1) {
        int t = (threadIdx.x >= off) ? sh[threadIdx.x - off] : 0;
        __syncthreads();
        sh[threadIdx.x] += t;
        __syncthreads();
    }
    if (threadIdx.x < nb) bsums[threadIdx.x] = sh[threadIdx.x] - v;
}
__global__ void scan3_k(int* __restrict__ rp, const int* __restrict__ bsums,
                        int* __restrict__ cur, int n, int total) {
    int i = blockIdx.x * blockDim.x + threadIdx.x;
    if (i < n) {
        rp[i] += bsums[i >> 10];
        cur[i] = 0;
    }
    if (i == 0) rp[n] = total;
}
__global__ void fill_k(int et) {
    int e = blockIdx.x * blockDim.x + threadIdx.x;
    if (e >= et) return;
    int d = g_dst[e];
    int slot = g_rp[d] + atomicAdd(&g_cur[d], 1);
    g_csrc[slot] = g_src[e];
}

// ---------------- W transpose + bf16 split ----------------------------------
__global__ void wt_k(const float* __restrict__ W, __nv_bfloat16* __restrict__ hi,
                     __nv_bfloat16* __restrict__ lo, int K, int NT) {
    int idx = blockIdx.x * blockDim.x + threadIdx.x;
    if (idx >= K * NT) return;
    int n = idx / K, k = idx - n * K;
    float v = W[(size_t)k * NT + n];
    __nv_bfloat16 h = __float2bfloat16_rn(v);
    float r = v - __bfloat162float(h);
    hi[idx] = h;
    lo[idx] = __float2bfloat16_rn(r);
}

// ---------------- A split: fp32 -> bf16 hi/lo (layer 0 input only) ----------
__global__ void asplit_k(const float* __restrict__ A,
                         __nv_bfloat16* __restrict__ hi,
                         __nv_bfloat16* __restrict__ lo, int total4) {
    int i = blockIdx.x * blockDim.x + threadIdx.x;
    if (i >= total4) return;
    float4 v = reinterpret_cast<const float4*>(A)[i];
    uint2 hp, lp;
    __nv_bfloat16 h0 = __float2bfloat16_rn(v.x);
    __nv_bfloat16 h1 = __float2bfloat16_rn(v.y);
    __nv_bfloat16 h2 = __float2bfloat16_rn(v.z);
    __nv_bfloat16 h3 = __float2bfloat16_rn(v.w);
    hp.x = pack_bf16(v.x, v.y);
    hp.y = pack_bf16(v.z, v.w);
    lp.x = pack_bf16(v.x - __bfloat162float(h0), v.y - __bfloat162float(h1));
    lp.y = pack_bf16(v.z - __bfloat162float(h2), v.w - __bfloat162float(h3));
    reinterpret_cast<uint2*>(hi)[i] = hp;
    reinterpret_cast<uint2*>(lo)[i] = lp;
}

// ---------------- HMMA split-bf16 GEMM (128x128 tile, warp 32x64) ------------
// SMEM stage layout (BKP=40 bf16 padded rows):
//   [0,10240)      A-hi  128 x 32
//   [10240,20480)  A-lo
//   [20480,30720)  B-hi  128 x 32
//   [30720,40960)  B-lo
__device__ __forceinline__ void stage_ldg(
    const __nv_bfloat16* __restrict__ Ahi, const __nv_bfloat16* __restrict__ Alo,
    const __nv_bfloat16* __restrict__ Bhi, const __nv_bfloat16* __restrict__ Blo,
    int ctaM, int ctaN, int kc, int M, int NT, int Kdim, int t,
    uint4 av[4], uint4 bv[4]) {
    int r = t >> 1, kg = (t & 1) * 16;
    int row = ctaM + r;
    if (row < M) {
        const __nv_bfloat16* p = Ahi + (size_t)row * Kdim + kc + kg;
        av[0] = *(const uint4*)p;
        av[1] = *(const uint4*)(p + 8);
        const __nv_bfloat16* q = Alo + (size_t)row * Kdim + kc + kg;
        av[2] = *(const uint4*)q;
        av[3] = *(const uint4*)(q + 8);
    } else {
        av[0] = av[1] = av[2] = av[3] = make_uint4(0, 0, 0, 0);
    }
    int n = t & 127, g = t >> 7;          // B row, 16-col group
    int gn = ctaN + n;
    if (gn < NT) {
        const __nv_bfloat16* ph = Bhi + (size_t)gn * Kdim + kc + g * 16;
        bv[0] = *(const uint4*)ph;
        bv[1] = *(const uint4*)(ph + 8);
        const __nv_bfloat16* pl = Blo + (size_t)gn * Kdim + kc + g * 16;
        bv[2] = *(const uint4*)pl;
        bv[3] = *(const uint4*)(pl + 8);
    } else {
        bv[0] = bv[1] = bv[2] = bv[3] = make_uint4(0, 0, 0, 0);
    }
}

__device__ __forceinline__ void stage_sts(char* smem, int s, int t,
                                          const uint4 av[4], const uint4 bv[4]) {
    char* base = smem + s * STG_BYTES;
    int r = t >> 1, kg = (t & 1) * 16;
    uint32_t off = (uint32_t)(r * BKP + kg) * 2;
    *(uint4*)(base + off)              = av[0];
    *(uint4*)(base + off + 16)         = av[1];
    *(uint4*)(base + 10240 + off)      = av[2];
    *(uint4*)(base + 10240 + off + 16) = av[3];
    int n = t & 127, g = t >> 7;
    uint32_t boff = (uint32_t)(n * BKP + g * 16) * 2;
    *(uint4*)(base + 20480 + boff)      = bv[0];
    *(uint4*)(base + 20480 + boff + 16) = bv[1];
    *(uint4*)(base + 30720 + boff)      = bv[2];
    *(uint4*)(base + 30720 + boff + 16) = bv[3];
}

__global__ __launch_bounds__(256, 1)
void gemm_mma(const __nv_bfloat16* __restrict__ Ahi,
              const __nv_bfloat16* __restrict__ Alo,
              const __nv_bfloat16* __restrict__ Bhi,
              const __nv_bfloat16* __restrict__ Blo,
              __half* __restrict__ C,
              float* __restrict__ als, float* __restrict__ ald,
              const float* __restrict__ a_src, const float* __restrict__ a_dst,
              int M, int Kdim, int NT, int fuse_al) {
    extern __shared__ char smem[];
    const int t = threadIdx.x;
    const int wid = t >> 5, lane = t & 31;
    const int wm = wid & 3, wn = wid >> 2;   // 4 warps m (32 rows), 2 warps n (64 cols)
    const int ctaM = blockIdx.y * BM;
    const int ctaN = blockIdx.x * BN;
    const uint32_t sb = smem_to_u32(smem);

    float acc[2][8][4];
#pragma unroll
    for (int i = 0; i < 2; i++)
#pragma unroll
        for (int j = 0; j < 8; j++)
#pragma unroll
            for (int k = 0; k < 4; k++) acc[i][j][k] = 0.f;

    const int nk = Kdim / BK;
    uint4 av[4], bv[4];

    stage_ldg(Ahi, Alo, Bhi, Blo, ctaM, ctaN, 0, M, NT, Kdim, t, av, bv);
    stage_sts(smem, 0, t, av, bv);
    __syncthreads();

    for (int i = 0; i < nk; i++) {
        if (i + 1 < nk)
            stage_ldg(Ahi, Alo, Bhi, Blo, ctaM, ctaN, (i + 1) * BK, M, NT, Kdim, t,
                      av, bv);

        const uint32_t sBase = sb + (uint32_t)((i & 1) * STG_BYTES);
#pragma unroll
        for (int kk = 0; kk < 2; kk++) {
            const int kb = kk * 16;
            uint32_t ah[2][4], alr[2][4];
#pragma unroll
            for (int mt = 0; mt < 2; mt++) {
                int row_in = wm * 32 + mt * 16 + (lane & 15);
                int koff = kb + ((lane >> 4) << 3);
                uint32_t off = (uint32_t)(row_in * BKP + koff) * 2;
                ldsm4(ah[mt], sBase + off);
                ldsm4(alr[mt], sBase + 10240 + off);
            }
            uint32_t bh[8][2], bl[8][2];
#pragma unroll
            for (int nt2 = 0; nt2 < 4; nt2++) {
                int n_in = wn * 64 + nt2 * 16 + ((lane >> 4) << 3) + (lane & 7);
                int koff = kb + ((lane >> 3) & 1) * 8;
                uint32_t off = (uint32_t)(n_in * BKP + koff) * 2;
                uint32_t r[4];
                ldsm4(r, sBase + 20480 + off);
                bh[nt2 * 2][0] = r[0]; bh[nt2 * 2][1] = r[1];
                bh[nt2 * 2 + 1][0] = r[2]; bh[nt2 * 2 + 1][1] = r[3];
                ldsm4(r, sBase + 30720 + off);
                bl[nt2 * 2][0] = r[0]; bl[nt2 * 2][1] = r[1];
                bl[nt2 * 2 + 1][0] = r[2]; bl[nt2 * 2 + 1][1] = r[3];
            }
#pragma unroll
            for (int mt = 0; mt < 2; mt++)
#pragma unroll
                for (int nt = 0; nt < 8; nt++) {
                    mma_bf16(acc[mt][nt], ah[mt], bh[nt]);
                    mma_bf16(acc[mt][nt], ah[mt], bl[nt]);
                    mma_bf16(acc[mt][nt], alr[mt], bh[nt]);
                }
        }

        if (i + 1 < nk)
            stage_sts(smem, (i + 1) & 1, t, av, bv);
        __syncthreads();
    }

    // ---- epilogue: write C (fp16) + fused attention logits ----
    // Warp covers 64 cols = 2 heads (C=32); reduce per head-group of 4 nt.
    const int grp = lane >> 2, q = lane & 3;
#pragma unroll
    for (int mt = 0; mt < 2; mt++) {
#pragma unroll
        for (int half = 0; half < 2; half++) {
            int row = ctaM + wm * 32 + mt * 16 + grp + half * 8;
#pragma unroll
            for (int hg = 0; hg < 2; hg++) {
                float as_p = 0.f, ad_p = 0.f;
#pragma unroll
                for (int nt4 = 0; nt4 < 4; nt4++) {
                    int nt = hg * 4 + nt4;
                    int gcol = ctaN + wn * 64 + nt * 8 + q * 2;
                    float v0 = acc[mt][nt][half * 2 + 0];
                    float v1 = acc[mt][nt][half * 2 + 1];
                    if (row < M && gcol + 1 < NT + 1 && gcol < NT)
                        *(__half2*)&C[(size_t)row * NT + gcol] = __floats2half2_rn(v0, v1);
                    if (fuse_al) {
                        as_p += v0 * a_src[gcol] + v1 * a_src[gcol + 1];
                        ad_p += v0 * a_dst[gcol] + v1 * a_dst[gcol + 1];
                    }
                }
                if (fuse_al) {
                    as_p += __shfl_xor_sync(0xffffffffu, as_p, 1);
                    as_p += __shfl_xor_sync(0xffffffffu, as_p, 2);
                    ad_p += __shfl_xor_sync(0xffffffffu, ad_p, 1);
                    ad_p += __shfl_xor_sync(0xffffffffu, ad_p, 2);
                    int head = (ctaN + wn * 64 + hg * 32) >> 5;
                    if (q == 0 && row < M) {
                        als[(size_t)row * 8 + head] = as_p;
                        ald[(size_t)row * 8 + head] = ad_p;
                    }
                }
            }
        }
    }
}

// ---------------- attention logits for layer 2 (H=1, C=40, fp16 x) ----------
__global__ void compute_al2_h(const __half* __restrict__ x,
                              const float* __restrict__ a_src,
                              const float* __restrict__ a_dst,
                              float* __restrict__ als, float* __restrict__ ald,
                              int Nn) {
    int n = (blockIdx.x * blockDim.x + threadIdx.x) >> 5;
    int lane = threadIdx.x & 31;
    if (n >= Nn) return;
    const __half* xp = x + (size_t)n * 40;
    float vs = 0.f, vd = 0.f;
    for (int c = lane; c < 40; c += 32) {
        float xv = __half2float(xp[c]);
        vs += xv * a_src[c];
        vd += xv * a_dst[c];
    }
#pragma unroll
    for (int off = 16; off > 0; off >>= 1) {
        vs += __shfl_xor_sync(0xffffffffu, vs, off);
        vd += __shfl_xor_sync(0xffffffffu, vd, off);
    }
    if (lane == 0) { als[n] = vs; ald[n] = vd; }
}

// ------- fused SINGLE-PASS softmax + aggregate + bias(+elu): warp per dst ---
template <int H, int C, int OUTMODE>
__global__ void gat_agg_h(const __half* __restrict__ x,
                          const float* __restrict__ als,
                          const float* __restrict__ ald,
                          const int* __restrict__ rp,
                          const int* __restrict__ cs,
                          float* __restrict__ out,
                          __nv_bfloat16* __restrict__ ohi,
                          __nv_bfloat16* __restrict__ olo,
                          const float* __restrict__ bias,
                          int Nn, int do_elu) {
    constexpr int HC = H * C;
    int n = (blockIdx.x * blockDim.x + threadIdx.x) >> 5;
    int lane = threadIdx.x & 31;
    if (n >= Nn) return;

    int start = rp[n], end = rp[n + 1];
    float aldv = (lane < H) ? ald[n * H + lane] : 0.f;

    const int col0 = lane * 8;
    const bool act = col0 < HC;
    const int alane = act ? (col0 / C) : 0;
    float acc[8];
#pragma unroll
    for (int i = 0; i < 8; i++) acc[i] = 0.f;
    float sacc = 0.f;

#pragma unroll 4
    for (int k = start; k < end; k++) {
        int src = cs[k];
        float e = 0.f;
        if (lane < H) {
            float v = als[src * H + lane] + aldv;
            v = v > 0.f ? v : 0.2f * v;
            e = __expf(v);
            sacc += e;
        }
        float a = __shfl_sync(0xffffffffu, e, alane);
        if (act) {
            uint4 vv = *(const uint4*)(x + (size_t)src * HC + col0);
            float2 f0 = __half22float2(*(__half2*)&vv.x);
            float2 f1 = __half22float2(*(__half2*)&vv.y);
            float2 f2 = __half22float2(*(__half2*)&vv.z);
            float2 f3 = __half22float2(*(__half2*)&vv.w);
            acc[0] += f0.x * a; acc[1] += f0.y * a;
            acc[2] += f1.x * a; acc[3] += f1.y * a;
            acc[4] += f2.x * a; acc[5] += f2.y * a;
            acc[6] += f3.x * a; acc[7] += f3.y * a;
        }
    }

    float inv_s = (lane < H && sacc > 0.f) ? __frcp_rn(sacc) : 0.f;
    float scale = __shfl_sync(0xffffffffu, inv_s, alane);

    if (act) {
        float o[8];
#pragma unroll
        for (int i = 0; i < 8; i++) {
            float v = acc[i] * scale + bias[col0 + i];
            if (do_elu) v = v > 0.f ? v : expm1f(v);
            o[i] = v;
        }
        if (OUTMODE == 0) {
            float* od = out + (size_t)n * HC + col0;
            *(float4*)(od)     = make_float4(o[0], o[1], o[2], o[3]);
            *(float4*)(od + 4) = make_float4(o[4], o[5], o[6], o[7]);
        } else {
            uint4 hp, lp;
            float r[8];
#pragma unroll
            for (int i = 0; i < 8; i++) {
                __nv_bfloat16 h = __float2bfloat16_rn(o[i]);
                r[i] = o[i] - __bfloat162float(h);
            }
            hp.x = pack_bf16(o[0], o[1]); hp.y = pack_bf16(o[2], o[3]);
            hp.z = pack_bf16(o[4], o[5]); hp.w = pack_bf16(o[6], o[7]);
            lp.x = pack_bf16(r[0], r[1]); lp.y = pack_bf16(r[2], r[3]);
            lp.z = pack_bf16(r[4], r[5]); lp.w = pack_bf16(r[6], r[7]);
            *(uint4*)(ohi + (size_t)n * HC + col0) = hp;
            *(uint4*)(olo + (size_t)n * HC + col0) = lp;
        }
    }
}

// ---------------- launcher (single stream — graph-capture friendly) ---------
extern "C" void kernel_launch(void* const* d_in, const int* in_sizes, int n_in,
                              void* d_out, int out_size) {
    const float* feats = (const float*)d_in[0];
    const void*  ei    = d_in[1];
    const float* W0  = (const float*)d_in[2];
    const float* as0 = (const float*)d_in[3];
    const float* ad0 = (const float*)d_in[4];
    const float* b0  = (const float*)d_in[5];
    const float* W1  = (const float*)d_in[6];
    const float* as1 = (const float*)d_in[7];
    const float* ad1 = (const float*)d_in[8];
    const float* b1  = (const float*)d_in[9];
    const float* W2  = (const float*)d_in[10];
    const float* as2 = (const float*)d_in[11];
    const float* ad2 = (const float*)d_in[12];
    const float* b2  = (const float*)d_in[13];

    int N  = in_sizes[0] / FIN;
    int NE = in_sizes[1] / 2;
    int ET = NE + N;
    float* out = (float*)d_out;
    (void)n_in; (void)out_size;

    __half* pxh;
    float *pals, *pald;
    int *pdeg, *prp, *pcur, *pcs, *pbs;
    __nv_bfloat16 *pwh, *pwl, *pah, *pal;
    cudaGetSymbolAddress((void**)&pxh,  g_xh);
    cudaGetSymbolAddress((void**)&pals, g_als);
    cudaGetSymbolAddress((void**)&pald, g_ald);
    cudaGetSymbolAddress((void**)&pdeg, g_deg);
    cudaGetSymbolAddress((void**)&prp,  g_rp);
    cudaGetSymbolAddress((void**)&pcur, g_cur);
    cudaGetSymbolAddress((void**)&pcs,  g_csrc);
    cudaGetSymbolAddress((void**)&pbs,  g_bs);
    cudaGetSymbolAddress((void**)&pwh,  g_wthi);
    cudaGetSymbolAddress((void**)&pwl,  g_wtlo);
    cudaGetSymbolAddress((void**)&pah,  g_ahi);
    cudaGetSymbolAddress((void**)&pal,  g_alo);

    cudaFuncSetAttribute(gemm_mma, cudaFuncAttributeMaxDynamicSharedMemorySize, SM_GEMM);

    int ethreads = (ET + 255) / 256;
    int nwarps_b = (N * 32 + 255) / 256;
    dim3 grid256(1, (N + BM - 1) / BM);
    grid256.x = (256 + BN - 1) / BN;     // 2
    dim3 grid40(1, (N + BM - 1) / BM);   // 1 col-block for NT=40

    // (1) dtype detect + zero(deg)
    detect_zero_k<<<256, 256>>>((const unsigned int*)ei, pdeg, N + 1);
    // (2) layer-0 weights
    wt_k<<<(256 * 128 + 255) / 256, 256>>>(W0, pwh + 0 * 65536, pwl + 0 * 65536, 128, 256);
    // (3) layer-0 A split
    asplit_k<<<(N * 128 / 4 + 255) / 256, 256>>>(feats, pah, pal, N * 128 / 4);
    // (4) layer-0 GEMM  <-- profiled launch
    gemm_mma<<<grid256, 256, SM_GEMM>>>(pah, pal, pwh, pwl, pxh, pals, pald,
                                        as0, ad0, N, 128, 256, 1);

    // --- CSR build (must complete before agg0) ---
    decode_count_k<<<ethreads, 256>>>(ei, NE, N);
    int nb1 = (N + 1023) / 1024;
    scan1_k<<<nb1, 1024>>>(pdeg, prp, pbs, N);
    scan2_k<<<1, 256>>>(pbs, nb1);
    scan3_k<<<(N + 255) / 256, 256>>>(prp, pbs, pcur, N, ET);
    fill_k<<<ethreads, 256>>>(ET);

    // --- layer 0 aggregation ---
    gat_agg_h<8, 32, 1><<<nwarps_b, 256>>>(pxh, pals, pald, prp, pcs,
                                           nullptr, pah, pal, b0, N, 1);

    // --- layer 1: 256 -> 8x32 ---
    wt_k<<<(256 * 256 + 255) / 256, 256>>>(W1, pwh + 1 * 65536, pwl + 1 * 65536, 256, 256);
    gemm_mma<<<grid256, 256, SM_GEMM>>>(pah, pal, pwh + 65536, pwl + 65536, pxh,
                                        pals, pald, as1, ad1, N, 256, 256, 1);
    gat_agg_h<8, 32, 1><<<nwarps_b, 256>>>(pxh, pals, pald, prp, pcs,
                                           nullptr, pah, pal, b1, N, 1);

    // --- layer 2: 256 -> 1x40 ---
    wt_k<<<(40 * 256 + 255) / 256, 256>>>(W2, pwh + 2 * 65536, pwl + 2 * 65536, 256, 40);
    gemm_mma<<<grid40, 256, SM_GEMM>>>(pah, pal, pwh + 2 * 65536, pwl + 2 * 65536,
                                       pxh, pals, pald, as2, ad2, N, 256, 40, 0);
    compute_al2_h<<<nwarps_b, 256>>>(pxh, as2, ad2, pals, pald, N);
    gat_agg_h<1, 40, 0><<<nwarps_b, 256>>>(pxh, pals, pald, prp, pcs,
                                           out, nullptr, nullptr, b2, N, 0);
}

// round 10
// speedup vs baseline: 1.1570x; 1.1570x over previous
#include <cuda_runtime.h>
#include <cuda_bf16.h>
#include <cuda_fp16.h>
#include <cstdint>

#define FIN     128
#define NNODES  100000
#define NEDGE   1600000
#define ETOTMAX (NEDGE + NNODES)

#define BM 128
#define BN 64
#define BK 32
#define BKP 40            // padded SMEM row length (fp16 elems) = 80 bytes
#define STG_BYTES 20480   // per stage: A 10240 + Bhi 5120 + Blo 5120
#define SM_GEMM (2 * STG_BYTES)

// ---------------- scratch (static device globals; no runtime allocation) ----
__device__ __half g_xh[(size_t)NNODES * 256];   // GEMM output (fp16)
__device__ __half g_a16[(size_t)NNODES * 256];  // GEMM A operand (fp16)
__device__ float g_als[NNODES * 8];
__device__ float g_ald[NNODES * 8];
__device__ int   g_src[ETOTMAX];
__device__ int   g_dst[ETOTMAX];
__device__ int   g_deg[NNODES + 1];
__device__ int   g_rp[NNODES + 1];
__device__ int   g_cur[NNODES];
__device__ int   g_csrc[ETOTMAX];
__device__ int   g_bs[256];
__device__ int   g_is64;
__device__ __half g_wthi[3][256 * 256];         // per-layer weight hi (fp16)
__device__ __half g_wtlo[3][256 * 256];         // per-layer weight residual

// ======================= small PTX helpers ==================================
__device__ __forceinline__ uint32_t smem_to_u32(const void* p) {
    uint32_t a;
    asm("{ .reg .u64 t; cvta.to.shared.u64 t, %1; cvt.u32.u64 %0, t; }"
        : "=r"(a) : "l"(p));
    return a;
}
__device__ __forceinline__ void ldsm4(uint32_t* r, uint32_t addr) {
    asm volatile("ldmatrix.sync.aligned.m8n8.x4.shared.b16 {%0,%1,%2,%3}, [%4];"
                 : "=r"(r[0]), "=r"(r[1]), "=r"(r[2]), "=r"(r[3]) : "r"(addr));
}
__device__ __forceinline__ void mma_fp16(float* c, const uint32_t* a, const uint32_t* b) {
    asm volatile("mma.sync.aligned.m16n8k16.row.col.f32.f16.f16.f32 "
                 "{%0,%1,%2,%3}, {%4,%5,%6,%7}, {%8,%9}, {%0,%1,%2,%3};"
                 : "+f"(c[0]), "+f"(c[1]), "+f"(c[2]), "+f"(c[3])
                 : "r"(a[0]), "r"(a[1]), "r"(a[2]), "r"(a[3]), "r"(b[0]), "r"(b[1]));
}

// ------- detect edge dtype (block 0) + zero degree array (all blocks) -------
__global__ void detect_zero_k(const unsigned int* __restrict__ w,
                              int* __restrict__ deg, int n) {
    if (blockIdx.x == 0) {
        __shared__ int flag;
        if (threadIdx.x == 0) flag = 0;
        __syncthreads();
        int local = 0;
        for (int i = threadIdx.x; i < 2048; i += blockDim.x)
            if ((i & 1) && w[i]) local = 1;
        if (local) atomicOr(&flag, 1);
        __syncthreads();
        if (threadIdx.x == 0) g_is64 = flag ? 0 : 1;
    }
    for (int i = blockIdx.x * blockDim.x + threadIdx.x; i < n;
         i += gridDim.x * blockDim.x)
        deg[i] = 0;
}

__global__ void decode_count_k(const void* __restrict__ ei, int ne, int n) {
    int e = blockIdx.x * blockDim.x + threadIdx.x;
    int et = ne + n;
    if (e >= et) return;
    int s, d;
    if (e < ne) {
        if (g_is64) {
            const long long* p = (const long long*)ei;
            s = (int)p[e];
            d = (int)p[(size_t)ne + e];
        } else {
            const int* p = (const int*)ei;
            s = p[e];
            d = p[ne + e];
        }
    } else {
        s = e - ne; d = e - ne;
    }
    g_src[e] = s;
    g_dst[e] = d;
    atomicAdd(&g_deg[d], 1);
}

// ---------------- CSR build --------------------------------------------------
__global__ void scan1_k(const int* __restrict__ deg, int* __restrict__ ex,
                        int* __restrict__ bsums, int n) {
    __shared__ int sh[1024];
    int i = blockIdx.x * 1024 + threadIdx.x;
    int v = (i < n) ? deg[i] : 0;
    sh[threadIdx.x] = v;
    __syncthreads();
    for (int off = 1; off < 1024; off <<= 1) {
        int t = (threadIdx.x >= off) ? sh[threadIdx.x - off] : 0;
        __syncthreads();
        sh[threadIdx.x] += t;
        __syncthreads();
    }
    if (i < n) ex[i] = sh[threadIdx.x] - v;
    if (threadIdx.x == 1023) bsums[blockIdx.x] = sh[1023];
}
__global__ void scan2_k(int* __restrict__ bsums, int nb) {
    __shared__ int sh[256];
    int v = (threadIdx.x < nb) ? bsums[threadIdx.x] : 0;
    sh[threadIdx.x] = v;
    __syncthreads();
    for (int off = 1; off < 256; off <<= 1) {
        int t = (threadIdx.x >= off) ? sh[threadIdx.x - off] : 0;
        __syncthreads();
        sh[threadIdx.x] += t;
        __syncthreads();
    }
    if (threadIdx.x < nb) bsums[threadIdx.x] = sh[threadIdx.x] - v;
}
__global__ void scan3_k(int* __restrict__ rp, const int* __restrict__ bsums,
                        int* __restrict__ cur, int n, int total) {
    int i = blockIdx.x * blockDim.x + threadIdx.x;
    if (i < n) {
        rp[i] += bsums[i >> 10];
        cur[i] = 0;
    }
    if (i == 0) rp[n] = total;
}
__global__ void fill_k(int et) {
    int e = blockIdx.x * blockDim.x + threadIdx.x;
    if (e >= et) return;
    int d = g_dst[e];
    int slot = g_rp[d] + atomicAdd(&g_cur[d], 1);
    g_csrc[slot] = g_src[e];
}

// ---------------- W transpose + fp16 split ----------------------------------
__global__ void wt_k(const float* __restrict__ W, __half* __restrict__ hi,
                     __half* __restrict__ lo, int K, int NT) {
    int idx = blockIdx.x * blockDim.x + threadIdx.x;
    if (idx >= K * NT) return;
    int n = idx / K, k = idx - n * K;
    float v = W[(size_t)k * NT + n];
    __half h = __float2half_rn(v);
    hi[idx] = h;
    lo[idx] = __float2half_rn(v - __half2float(h));
}

// ---------------- A convert: fp32 -> fp16 (layer 0 input only) --------------
__global__ void asplit_k(const float* __restrict__ A, __half* __restrict__ o,
                         int total4) {
    int i = blockIdx.x * blockDim.x + threadIdx.x;
    if (i >= total4) return;
    float4 v = reinterpret_cast<const float4*>(A)[i];
    uint2 p;
    __half2 t0 = __floats2half2_rn(v.x, v.y);
    __half2 t1 = __floats2half2_rn(v.z, v.w);
    p.x = *reinterpret_cast<uint32_t*>(&t0);
    p.y = *reinterpret_cast<uint32_t*>(&t1);
    reinterpret_cast<uint2*>(o)[i] = p;
}

// ---------------- HMMA fp16 GEMM (A single fp16, W split hi/lo) --------------
// SMEM stage layout (BKP=40 fp16 padded rows):
//   [0,10240)      A    128 x 32
//   [10240,15360)  B-hi  64 x 32
//   [15360,20480)  B-lo
__device__ __forceinline__ void stage_ldg(
    const __half* __restrict__ A,
    const __half* __restrict__ Bhi, const __half* __restrict__ Blo,
    int ctaM, int ctaN, int kc, int M, int NT, int Kdim, int t,
    uint4 av[2], uint4& bv0, uint4& bv1) {
    int r = t >> 1, kg = (t & 1) * 16;
    int row = ctaM + r;
    if (row < M) {
        const __half* p = A + (size_t)row * Kdim + kc + kg;
        av[0] = *(const uint4*)p;
        av[1] = *(const uint4*)(p + 8);
    } else {
        av[0] = av[1] = make_uint4(0, 0, 0, 0);
    }
    int n = t & 63, sp = (t >> 6) & 1, hf = t >> 7;
    int gn = ctaN + n;
    const __half* B = sp ? Blo : Bhi;
    if (gn < NT) {
        const __half* q = B + (size_t)gn * Kdim + kc + hf * 16;
        bv0 = *(const uint4*)q;
        bv1 = *(const uint4*)(q + 8);
    } else {
        bv0 = make_uint4(0, 0, 0, 0);
        bv1 = make_uint4(0, 0, 0, 0);
    }
}

__device__ __forceinline__ void stage_sts(char* smem, int s, int t,
                                          const uint4 av[2], uint4 bv0, uint4 bv1) {
    char* base = smem + s * STG_BYTES;
    int r = t >> 1, kg = (t & 1) * 16;
    uint32_t off = (uint32_t)(r * BKP + kg) * 2;
    *(uint4*)(base + off)      = av[0];
    *(uint4*)(base + off + 16) = av[1];
    int n = t & 63, sp = (t >> 6) & 1, hf = t >> 7;
    uint32_t boff = (uint32_t)(n * BKP + hf * 16) * 2;
    char* bb = base + 10240 + sp * 5120;
    *(uint4*)(bb + boff)      = bv0;
    *(uint4*)(bb + boff + 16) = bv1;
}

__global__ __launch_bounds__(256, 2)
void gemm_mma(const __half* __restrict__ A,
              const __half* __restrict__ Bhi,
              const __half* __restrict__ Blo,
              __half* __restrict__ C,
              float* __restrict__ als, float* __restrict__ ald,
              const float* __restrict__ a_src, const float* __restrict__ a_dst,
              int M, int Kdim, int NT, int fuse_al) {
    extern __shared__ char smem[];
    const int t = threadIdx.x;
    const int wid = t >> 5, lane = t & 31;
    const int wm = wid & 3, wn = wid >> 2;   // 4 warps m (32 rows), 2 warps n (32 cols)
    const int ctaM = blockIdx.y * BM;
    const int ctaN = blockIdx.x * BN;
    const uint32_t sb = smem_to_u32(smem);

    float acc[2][4][4];
#pragma unroll
    for (int i = 0; i < 2; i++)
#pragma unroll
        for (int j = 0; j < 4; j++)
#pragma unroll
            for (int k = 0; k < 4; k++) acc[i][j][k] = 0.f;

    const int nk = Kdim / BK;
    uint4 av[2], bv0, bv1;

    stage_ldg(A, Bhi, Blo, ctaM, ctaN, 0, M, NT, Kdim, t, av, bv0, bv1);
    stage_sts(smem, 0, t, av, bv0, bv1);
    __syncthreads();

    for (int i = 0; i < nk; i++) {
        if (i + 1 < nk)
            stage_ldg(A, Bhi, Blo, ctaM, ctaN, (i + 1) * BK, M, NT, Kdim, t,
                      av, bv0, bv1);

        const uint32_t sBase = sb + (uint32_t)((i & 1) * STG_BYTES);
#pragma unroll
        for (int kk = 0; kk < 2; kk++) {
            const int kb = kk * 16;
            uint32_t ah[2][4];
#pragma unroll
            for (int mt = 0; mt < 2; mt++) {
                int row_in = wm * 32 + mt * 16 + (lane & 15);
                int koff = kb + ((lane >> 4) << 3);
                uint32_t off = (uint32_t)(row_in * BKP + koff) * 2;
                ldsm4(ah[mt], sBase + off);
            }
            uint32_t bh[4][2], bl[4][2];
#pragma unroll
            for (int nt2 = 0; nt2 < 2; nt2++) {
                int n_in = wn * 32 + nt2 * 16 + ((lane >> 4) << 3) + (lane & 7);
                int koff = kb + ((lane >> 3) & 1) * 8;
                uint32_t off = (uint32_t)(n_in * BKP + koff) * 2;
                uint32_t r[4];
                ldsm4(r, sBase + 10240 + off);
                bh[nt2 * 2][0] = r[0]; bh[nt2 * 2][1] = r[1];
                bh[nt2 * 2 + 1][0] = r[2]; bh[nt2 * 2 + 1][1] = r[3];
                ldsm4(r, sBase + 15360 + off);
                bl[nt2 * 2][0] = r[0]; bl[nt2 * 2][1] = r[1];
                bl[nt2 * 2 + 1][0] = r[2]; bl[nt2 * 2 + 1][1] = r[3];
            }
#pragma unroll
            for (int mt = 0; mt < 2; mt++)
#pragma unroll
                for (int nt = 0; nt < 4; nt++) {
                    mma_fp16(acc[mt][nt], ah[mt], bh[nt]);
                    mma_fp16(acc[mt][nt], ah[mt], bl[nt]);
                }
        }

        if (i + 1 < nk)
            stage_sts(smem, (i + 1) & 1, t, av, bv0, bv1);
        __syncthreads();
    }

    // ---- epilogue: write C (fp16) + fused attention logits ----
    const int grp = lane >> 2, q = lane & 3;
#pragma unroll
    for (int mt = 0; mt < 2; mt++) {
#pragma unroll
        for (int half = 0; half < 2; half++) {
            int row = ctaM + wm * 32 + mt * 16 + grp + half * 8;
            float as_p = 0.f, ad_p = 0.f;
#pragma unroll
            for (int nt = 0; nt < 4; nt++) {
                int gcol = ctaN + wn * 32 + nt * 8 + q * 2;
                float v0 = acc[mt][nt][half * 2 + 0];
                float v1 = acc[mt][nt][half * 2 + 1];
                if (row < M && gcol < NT)
                    *(__half2*)&C[(size_t)row * NT + gcol] = __floats2half2_rn(v0, v1);
                if (fuse_al) {
                    as_p += v0 * a_src[gcol] + v1 * a_src[gcol + 1];
                    ad_p += v0 * a_dst[gcol] + v1 * a_dst[gcol + 1];
                }
            }
            if (fuse_al) {
                as_p += __shfl_xor_sync(0xffffffffu, as_p, 1);
                as_p += __shfl_xor_sync(0xffffffffu, as_p, 2);
                ad_p += __shfl_xor_sync(0xffffffffu, ad_p, 1);
                ad_p += __shfl_xor_sync(0xffffffffu, ad_p, 2);
                int head = (ctaN + wn * 32) >> 5;
                if (q == 0 && row < M) {
                    als[(size_t)row * 8 + head] = as_p;
                    ald[(size_t)row * 8 + head] = ad_p;
                }
            }
        }
    }
}

// ---------------- attention logits for layer 2 (H=1, C=40, fp16 x) ----------
__global__ void compute_al2_h(const __half* __restrict__ x,
                              const float* __restrict__ a_src,
                              const float* __restrict__ a_dst,
                              float* __restrict__ als, float* __restrict__ ald,
                              int Nn) {
    int n = (blockIdx.x * blockDim.x + threadIdx.x) >> 5;
    int lane = threadIdx.x & 31;
    if (n >= Nn) return;
    const __half* xp = x + (size_t)n * 40;
    float vs = 0.f, vd = 0.f;
    for (int c = lane; c < 40; c += 32) {
        float xv = __half2float(xp[c]);
        vs += xv * a_src[c];
        vd += xv * a_dst[c];
    }
#pragma unroll
    for (int off = 16; off > 0; off >>= 1) {
        vs += __shfl_xor_sync(0xffffffffu, vs, off);
        vd += __shfl_xor_sync(0xffffffffu, vd, off);
    }
    if (lane == 0) { als[n] = vs; ald[n] = vd; }
}

// ------- fused SINGLE-PASS softmax + aggregate + bias(+elu): warp per dst ---
// OUTMODE 0: fp32 out; OUTMODE 1: fp16 out (next layer's GEMM A operand).
template <int H, int C, int OUTMODE>
__global__ void gat_agg_h(const __half* __restrict__ x,
                          const float* __restrict__ als,
                          const float* __restrict__ ald,
                          const int* __restrict__ rp,
                          const int* __restrict__ cs,
                          float* __restrict__ out,
                          __half* __restrict__ oh,
                          const float* __restrict__ bias,
                          int Nn, int do_elu) {
    constexpr int HC = H * C;
    int n = (blockIdx.x * blockDim.x + threadIdx.x) >> 5;
    int lane = threadIdx.x & 31;
    if (n >= Nn) return;

    int start = rp[n], end = rp[n + 1];
    float aldv = (lane < H) ? ald[n * H + lane] : 0.f;

    const int col0 = lane * 8;
    const bool act = col0 < HC;
    const int alane = act ? (col0 / C) : 0;
    float acc[8];
#pragma unroll
    for (int i = 0; i < 8; i++) acc[i] = 0.f;
    float sacc = 0.f;

#pragma unroll 4
    for (int k = start; k < end; k++) {
        int src = cs[k];
        float e = 0.f;
        if (lane < H) {
            float v = als[src * H + lane] + aldv;
            v = v > 0.f ? v : 0.2f * v;
            e = __expf(v);
            sacc += e;
        }
        float a = __shfl_sync(0xffffffffu, e, alane);
        if (act) {
            uint4 vv = *(const uint4*)(x + (size_t)src * HC + col0);
            float2 f0 = __half22float2(*(__half2*)&vv.x);
            float2 f1 = __half22float2(*(__half2*)&vv.y);
            float2 f2 = __half22float2(*(__half2*)&vv.z);
            float2 f3 = __half22float2(*(__half2*)&vv.w);
            acc[0] += f0.x * a; acc[1] += f0.y * a;
            acc[2] += f1.x * a; acc[3] += f1.y * a;
            acc[4] += f2.x * a; acc[5] += f2.y * a;
            acc[6] += f3.x * a; acc[7] += f3.y * a;
        }
    }

    float inv_s = (lane < H && sacc > 0.f) ? __frcp_rn(sacc) : 0.f;
    float scale = __shfl_sync(0xffffffffu, inv_s, alane);

    if (act) {
        float o[8];
#pragma unroll
        for (int i = 0; i < 8; i++) {
            float v = acc[i] * scale + bias[col0 + i];
            if (do_elu) v = v > 0.f ? v : expm1f(v);
            o[i] = v;
        }
        if (OUTMODE == 0) {
            float* od = out + (size_t)n * HC + col0;
            *(float4*)(od)     = make_float4(o[0], o[1], o[2], o[3]);
            *(float4*)(od + 4) = make_float4(o[4], o[5], o[6], o[7]);
        } else {
            uint4 p;
            __half2 t0 = __floats2half2_rn(o[0], o[1]);
            __half2 t1 = __floats2half2_rn(o[2], o[3]);
            __half2 t2 = __floats2half2_rn(o[4], o[5]);
            __half2 t3 = __floats2half2_rn(o[6], o[7]);
            p.x = *(uint32_t*)&t0; p.y = *(uint32_t*)&t1;
            p.z = *(uint32_t*)&t2; p.w = *(uint32_t*)&t3;
            *(uint4*)(oh + (size_t)n * HC + col0) = p;
        }
    }
}

// ---------------- launcher (single stream — graph-capture friendly) ---------
extern "C" void kernel_launch(void* const* d_in, const int* in_sizes, int n_in,
                              void* d_out, int out_size) {
    const float* feats = (const float*)d_in[0];
    const void*  ei    = d_in[1];
    const float* W0  = (const float*)d_in[2];
    const float* as0 = (const float*)d_in[3];
    const float* ad0 = (const float*)d_in[4];
    const float* b0  = (const float*)d_in[5];
    const float* W1  = (const float*)d_in[6];
    const float* as1 = (const float*)d_in[7];
    const float* ad1 = (const float*)d_in[8];
    const float* b1  = (const float*)d_in[9];
    const float* W2  = (const float*)d_in[10];
    const float* as2 = (const float*)d_in[11];
    const float* ad2 = (const float*)d_in[12];
    const float* b2  = (const float*)d_in[13];

    int N  = in_sizes[0] / FIN;
    int NE = in_sizes[1] / 2;
    int ET = NE + N;
    float* out = (float*)d_out;
    (void)n_in; (void)out_size;

    __half *pxh, *pa16, *pwh, *pwl;
    float *pals, *pald;
    int *pdeg, *prp, *pcur, *pcs, *pbs;
    cudaGetSymbolAddress((void**)&pxh,  g_xh);
    cudaGetSymbolAddress((void**)&pa16, g_a16);
    cudaGetSymbolAddress((void**)&pals, g_als);
    cudaGetSymbolAddress((void**)&pald, g_ald);
    cudaGetSymbolAddress((void**)&pdeg, g_deg);
    cudaGetSymbolAddress((void**)&prp,  g_rp);
    cudaGetSymbolAddress((void**)&pcur, g_cur);
    cudaGetSymbolAddress((void**)&pcs,  g_csrc);
    cudaGetSymbolAddress((void**)&pbs,  g_bs);
    cudaGetSymbolAddress((void**)&pwh,  g_wthi);
    cudaGetSymbolAddress((void**)&pwl,  g_wtlo);

    cudaFuncSetAttribute(gemm_mma, cudaFuncAttributeMaxDynamicSharedMemorySize, SM_GEMM);

    int ethreads = (ET + 255) / 256;
    int nwarps_b = (N * 32 + 255) / 256;
    dim3 grid256(4, (N + BM - 1) / BM);
    dim3 grid40(1, (N + BM - 1) / BM);

    // (1) dtype detect + zero(deg)
    detect_zero_k<<<256, 256>>>((const unsigned int*)ei, pdeg, N + 1);
    // (2) layer-0 weights
    wt_k<<<(256 * 128 + 255) / 256, 256>>>(W0, pwh + 0 * 65536, pwl + 0 * 65536, 128, 256);
    // (3) layer-0 A convert
    asplit_k<<<(N * 128 / 4 + 255) / 256, 256>>>(feats, pa16, N * 128 / 4);
    // (4) layer-0 GEMM  <-- profiled launch
    gemm_mma<<<grid256, 256, SM_GEMM>>>(pa16, pwh, pwl, pxh, pals, pald,
                                        as0, ad0, N, 128, 256, 1);

    // --- CSR build (must complete before agg0) ---
    decode_count_k<<<ethreads, 256>>>(ei, NE, N);
    int nb1 = (N + 1023) / 1024;
    scan1_k<<<nb1, 1024>>>(pdeg, prp, pbs, N);
    scan2_k<<<1, 256>>>(pbs, nb1);
    scan3_k<<<(N + 255) / 256, 256>>>(prp, pbs, pcur, N, ET);
    fill_k<<<ethreads, 256>>>(ET);

    // --- layer 0 aggregation (writes fp16 A for layer 1) ---
    gat_agg_h<8, 32, 1><<<nwarps_b, 256>>>(pxh, pals, pald, prp, pcs,
                                           nullptr, pa16, b0, N, 1);

    // --- layer 1: 256 -> 8x32 ---
    wt_k<<<(256 * 256 + 255) / 256, 256>>>(W1, pwh + 1 * 65536, pwl + 1 * 65536, 256, 256);
    gemm_mma<<<grid256, 256, SM_GEMM>>>(pa16, pwh + 65536, pwl + 65536, pxh,
                                        pals, pald, as1, ad1, N, 256, 256, 1);
    gat_agg_h<8, 32, 1><<<nwarps_b, 256>>>(pxh, pals, pald, prp, pcs,
                                           nullptr, pa16, b1, N, 1);

    // --- layer 2: 256 -> 1x40 ---
    wt_k<<<(40 * 256 + 255) / 256, 256>>>(W2, pwh + 2 * 65536, pwl + 2 * 65536, 256, 40);
    gemm_mma<<<grid40, 256, SM_GEMM>>>(pa16, pwh + 2 * 65536, pwl + 2 * 65536,
                                       pxh, pals, pald, as2, ad2, N, 256, 40, 0);
    compute_al2_h<<<nwarps_b, 256>>>(pxh, as2, ad2, pals, pald, N);
    gat_agg_h<1, 40, 0><<<nwarps_b, 256>>>(pxh, pals, pald, prp, pcs,
                                           out, nullptr, b2, N, 0);
}

// round 11
// speedup vs baseline: 1.2671x; 1.0951x over previous
#include <cuda_runtime.h>
#include <cuda_bf16.h>
#include <cuda_fp16.h>
#include <cstdint>

#define FIN     128
#define NNODES  100000
#define NEDGE   1600000
#define ETOTMAX (NEDGE + NNODES)

#define BM 128
#define BN 64
#define BK 32
#define BKP 40            // padded SMEM row length (fp16 elems) = 80 bytes
#define STG_BYTES 15360   // per stage: A 10240 + B 5120
#define SM_GEMM (2 * STG_BYTES)

// ---------------- scratch (static device globals; no runtime allocation) ----
__device__ __half g_xh[(size_t)NNODES * 256];   // GEMM output (fp16)
__device__ __half g_a16[(size_t)NNODES * 256];  // GEMM A operand (fp16)
__device__ float g_als[NNODES * 8];
__device__ float g_ald[NNODES * 8];
__device__ int   g_src[ETOTMAX];
__device__ int   g_dst[ETOTMAX];
__device__ int   g_deg[NNODES + 1];
__device__ int   g_rp[NNODES + 1];
__device__ int   g_cur[NNODES];
__device__ int   g_csrc[ETOTMAX];
__device__ int   g_bs[256];
__device__ int   g_is64;
__device__ __half g_wt[3][256 * 256];           // per-layer weight (fp16, [N,K])

// ======================= small PTX helpers ==================================
__device__ __forceinline__ uint32_t smem_to_u32(const void* p) {
    uint32_t a;
    asm("{ .reg .u64 t; cvta.to.shared.u64 t, %1; cvt.u32.u64 %0, t; }"
        : "=r"(a) : "l"(p));
    return a;
}
__device__ __forceinline__ void ldsm4(uint32_t* r, uint32_t addr) {
    asm volatile("ldmatrix.sync.aligned.m8n8.x4.shared.b16 {%0,%1,%2,%3}, [%4];"
                 : "=r"(r[0]), "=r"(r[1]), "=r"(r[2]), "=r"(r[3]) : "r"(addr));
}
__device__ __forceinline__ void mma_fp16(float* c, const uint32_t* a, const uint32_t* b) {
    asm volatile("mma.sync.aligned.m16n8k16.row.col.f32.f16.f16.f32 "
                 "{%0,%1,%2,%3}, {%4,%5,%6,%7}, {%8,%9}, {%0,%1,%2,%3};"
                 : "+f"(c[0]), "+f"(c[1]), "+f"(c[2]), "+f"(c[3])
                 : "r"(a[0]), "r"(a[1]), "r"(a[2]), "r"(a[3]), "r"(b[0]), "r"(b[1]));
}

// ------- detect edge dtype (block 0) + zero degree array (all blocks) -------
__global__ void detect_zero_k(const unsigned int* __restrict__ w,
                              int* __restrict__ deg, int n) {
    if (blockIdx.x == 0) {
        __shared__ int flag;
        if (threadIdx.x == 0) flag = 0;
        __syncthreads();
        int local = 0;
        for (int i = threadIdx.x; i < 2048; i += blockDim.x)
            if ((i & 1) && w[i]) local = 1;
        if (local) atomicOr(&flag, 1);
        __syncthreads();
        if (threadIdx.x == 0) g_is64 = flag ? 0 : 1;
    }
    for (int i = blockIdx.x * blockDim.x + threadIdx.x; i < n;
         i += gridDim.x * blockDim.x)
        deg[i] = 0;
}

__global__ void decode_count_k(const void* __restrict__ ei, int ne, int n) {
    int e = blockIdx.x * blockDim.x + threadIdx.x;
    int et = ne + n;
    if (e >= et) return;
    int s, d;
    if (e < ne) {
        if (g_is64) {
            const long long* p = (const long long*)ei;
            s = (int)p[e];
            d = (int)p[(size_t)ne + e];
        } else {
            const int* p = (const int*)ei;
            s = p[e];
            d = p[ne + e];
        }
    } else {
        s = e - ne; d = e - ne;
    }
    g_src[e] = s;
    g_dst[e] = d;
    atomicAdd(&g_deg[d], 1);
}

// ---------------- CSR build --------------------------------------------------
__global__ void scan1_k(const int* __restrict__ deg, int* __restrict__ ex,
                        int* __restrict__ bsums, int n) {
    __shared__ int sh[1024];
    int i = blockIdx.x * 1024 + threadIdx.x;
    int v = (i < n) ? deg[i] : 0;
    sh[threadIdx.x] = v;
    __syncthreads();
    for (int off = 1; off < 1024; off <<= 1) {
        int t = (threadIdx.x >= off) ? sh[threadIdx.x - off] : 0;
        __syncthreads();
        sh[threadIdx.x] += t;
        __syncthreads();
    }
    if (i < n) ex[i] = sh[threadIdx.x] - v;
    if (threadIdx.x == 1023) bsums[blockIdx.x] = sh[1023];
}
__global__ void scan2_k(int* __restrict__ bsums, int nb) {
    __shared__ int sh[256];
    int v = (threadIdx.x < nb) ? bsums[threadIdx.x] : 0;
    sh[threadIdx.x] = v;
    __syncthreads();
    for (int off = 1; off < 256; off <<= 1) {
        int t = (threadIdx.x >= off) ? sh[threadIdx.x - off] : 0;
        __syncthreads();
        sh[threadIdx.x] += t;
        __syncthreads();
    }
    if (threadIdx.x < nb) bsums[threadIdx.x] = sh[threadIdx.x] - v;
}
__global__ void scan3_k(int* __restrict__ rp, const int* __restrict__ bsums,
                        int* __restrict__ cur, int n, int total) {
    int i = blockIdx.x * blockDim.x + threadIdx.x;
    if (i < n) {
        rp[i] += bsums[i >> 10];
        cur[i] = 0;
    }
    if (i == 0) rp[n] = total;
}
__global__ void fill_k(int et) {
    int e = blockIdx.x * blockDim.x + threadIdx.x;
    if (e >= et) return;
    int d = g_dst[e];
    int slot = g_rp[d] + atomicAdd(&g_cur[d], 1);
    g_csrc[slot] = g_src[e];
}

// ---------------- W transpose -> fp16 [N,K] ----------------------------------
__global__ void wt_k(const float* __restrict__ W, __half* __restrict__ o,
                     int K, int NT) {
    int idx = blockIdx.x * blockDim.x + threadIdx.x;
    if (idx >= K * NT) return;
    int n = idx / K, k = idx - n * K;
    o[idx] = __float2half_rn(W[(size_t)k * NT + n]);
}

// ---------------- A convert: fp32 -> fp16 (layer 0 input only) --------------
__global__ void asplit_k(const float* __restrict__ A, __half* __restrict__ o,
                         int total4) {
    int i = blockIdx.x * blockDim.x + threadIdx.x;
    if (i >= total4) return;
    float4 v = reinterpret_cast<const float4*>(A)[i];
    uint2 p;
    __half2 t0 = __floats2half2_rn(v.x, v.y);
    __half2 t1 = __floats2half2_rn(v.z, v.w);
    p.x = *reinterpret_cast<uint32_t*>(&t0);
    p.y = *reinterpret_cast<uint32_t*>(&t1);
    reinterpret_cast<uint2*>(o)[i] = p;
}

// ---------------- HMMA fp16 GEMM (pure fp16, 1 MMA per k16) ------------------
// SMEM stage layout (BKP=40 fp16 padded rows):
//   [0,10240)      A  128 x 32
//   [10240,15360)  B   64 x 32
__device__ __forceinline__ void stage_ldg(
    const __half* __restrict__ A, const __half* __restrict__ B,
    int ctaM, int ctaN, int kc, int M, int NT, int Kdim, int t,
    uint4 av[2], uint4 bv[2]) {
    int r = t >> 1, kg = (t & 1) * 16;
    int row = ctaM + r;
    if (row < M) {
        const __half* p = A + (size_t)row * Kdim + kc + kg;
        av[0] = *(const uint4*)p;
        av[1] = *(const uint4*)(p + 8);
    } else {
        av[0] = av[1] = make_uint4(0, 0, 0, 0);
    }
    if (t < 128) {
        int n = t & 63, hf = t >> 6;
        int gn = ctaN + n;
        if (gn < NT) {
            const __half* q = B + (size_t)gn * Kdim + kc + hf * 16;
            bv[0] = *(const uint4*)q;
            bv[1] = *(const uint4*)(q + 8);
        } else {
            bv[0] = bv[1] = make_uint4(0, 0, 0, 0);
        }
    }
}

__device__ __forceinline__ void stage_sts(char* smem, int s, int t,
                                          const uint4 av[2], const uint4 bv[2]) {
    char* base = smem + s * STG_BYTES;
    int r = t >> 1, kg = (t & 1) * 16;
    uint32_t off = (uint32_t)(r * BKP + kg) * 2;
    *(uint4*)(base + off)      = av[0];
    *(uint4*)(base + off + 16) = av[1];
    if (t < 128) {
        int n = t & 63, hf = t >> 6;
        uint32_t boff = (uint32_t)(n * BKP + hf * 16) * 2;
        *(uint4*)(base + 10240 + boff)      = bv[0];
        *(uint4*)(base + 10240 + boff + 16) = bv[1];
    }
}

__global__ __launch_bounds__(256, 2)
void gemm_mma(const __half* __restrict__ A,
              const __half* __restrict__ B,
              __half* __restrict__ C,
              float* __restrict__ als, float* __restrict__ ald,
              const float* __restrict__ a_src, const float* __restrict__ a_dst,
              int M, int Kdim, int NT, int fuse_al) {
    extern __shared__ char smem[];
    const int t = threadIdx.x;
    const int wid = t >> 5, lane = t & 31;
    const int wm = wid & 3, wn = wid >> 2;   // 4 warps m (32 rows), 2 warps n (32 cols)
    const int ctaM = blockIdx.y * BM;
    const int ctaN = blockIdx.x * BN;
    const uint32_t sb = smem_to_u32(smem);

    float acc[2][4][4];
#pragma unroll
    for (int i = 0; i < 2; i++)
#pragma unroll
        for (int j = 0; j < 4; j++)
#pragma unroll
            for (int k = 0; k < 4; k++) acc[i][j][k] = 0.f;

    const int nk = Kdim / BK;
    uint4 av[2], bv[2];

    stage_ldg(A, B, ctaM, ctaN, 0, M, NT, Kdim, t, av, bv);
    stage_sts(smem, 0, t, av, bv);
    __syncthreads();

    for (int i = 0; i < nk; i++) {
        if (i + 1 < nk)
            stage_ldg(A, B, ctaM, ctaN, (i + 1) * BK, M, NT, Kdim, t, av, bv);

        const uint32_t sBase = sb + (uint32_t)((i & 1) * STG_BYTES);
#pragma unroll
        for (int kk = 0; kk < 2; kk++) {
            const int kb = kk * 16;
            uint32_t ah[2][4];
#pragma unroll
            for (int mt = 0; mt < 2; mt++) {
                int row_in = wm * 32 + mt * 16 + (lane & 15);
                int koff = kb + ((lane >> 4) << 3);
                uint32_t off = (uint32_t)(row_in * BKP + koff) * 2;
                ldsm4(ah[mt], sBase + off);
            }
            uint32_t bh[4][2];
#pragma unroll
            for (int nt2 = 0; nt2 < 2; nt2++) {
                int n_in = wn * 32 + nt2 * 16 + ((lane >> 4) << 3) + (lane & 7);
                int koff = kb + ((lane >> 3) & 1) * 8;
                uint32_t off = (uint32_t)(n_in * BKP + koff) * 2;
                uint32_t r[4];
                ldsm4(r, sBase + 10240 + off);
                bh[nt2 * 2][0] = r[0]; bh[nt2 * 2][1] = r[1];
                bh[nt2 * 2 + 1][0] = r[2]; bh[nt2 * 2 + 1][1] = r[3];
            }
#pragma unroll
            for (int mt = 0; mt < 2; mt++)
#pragma unroll
                for (int nt = 0; nt < 4; nt++)
                    mma_fp16(acc[mt][nt], ah[mt], bh[nt]);
        }

        if (i + 1 < nk)
            stage_sts(smem, (i + 1) & 1, t, av, bv);
        __syncthreads();
    }

    // ---- epilogue: write C (fp16) + fused attention logits ----
    const int grp = lane >> 2, q = lane & 3;
#pragma unroll
    for (int mt = 0; mt < 2; mt++) {
#pragma unroll
        for (int half = 0; half < 2; half++) {
            int row = ctaM + wm * 32 + mt * 16 + grp + half * 8;
            float as_p = 0.f, ad_p = 0.f;
#pragma unroll
            for (int nt = 0; nt < 4; nt++) {
                int gcol = ctaN + wn * 32 + nt * 8 + q * 2;
                float v0 = acc[mt][nt][half * 2 + 0];
                float v1 = acc[mt][nt][half * 2 + 1];
                if (row < M && gcol < NT)
                    *(__half2*)&C[(size_t)row * NT + gcol] = __floats2half2_rn(v0, v1);
                if (fuse_al) {
                    as_p += v0 * a_src[gcol] + v1 * a_src[gcol + 1];
                    ad_p += v0 * a_dst[gcol] + v1 * a_dst[gcol + 1];
                }
            }
            if (fuse_al) {
                as_p += __shfl_xor_sync(0xffffffffu, as_p, 1);
                as_p += __shfl_xor_sync(0xffffffffu, as_p, 2);
                ad_p += __shfl_xor_sync(0xffffffffu, ad_p, 1);
                ad_p += __shfl_xor_sync(0xffffffffu, ad_p, 2);
                int head = (ctaN + wn * 32) >> 5;
                if (q == 0 && row < M) {
                    als[(size_t)row * 8 + head] = as_p;
                    ald[(size_t)row * 8 + head] = ad_p;
                }
            }
        }
    }
}

// ---------------- attention logits for layer 2 (H=1, C=40, fp16 x) ----------
__global__ void compute_al2_h(const __half* __restrict__ x,
                              const float* __restrict__ a_src,
                              const float* __restrict__ a_dst,
                              float* __restrict__ als, float* __restrict__ ald,
                              int Nn) {
    int n = (blockIdx.x * blockDim.x + threadIdx.x) >> 5;
    int lane = threadIdx.x & 31;
    if (n >= Nn) return;
    const __half* xp = x + (size_t)n * 40;
    float vs = 0.f, vd = 0.f;
    for (int c = lane; c < 40; c += 32) {
        float xv = __half2float(xp[c]);
        vs += xv * a_src[c];
        vd += xv * a_dst[c];
    }
#pragma unroll
    for (int off = 16; off > 0; off >>= 1) {
        vs += __shfl_xor_sync(0xffffffffu, vs, off);
        vd += __shfl_xor_sync(0xffffffffu, vd, off);
    }
    if (lane == 0) { als[n] = vs; ald[n] = vd; }
}

// ------- fused SINGLE-PASS softmax + aggregate + bias(+elu): warp per dst ---
// OUTMODE 0: fp32 out; OUTMODE 1: fp16 out (next layer's GEMM A operand).
template <int H, int C, int OUTMODE>
__global__ void gat_agg_h(const __half* __restrict__ x,
                          const float* __restrict__ als,
                          const float* __restrict__ ald,
                          const int* __restrict__ rp,
                          const int* __restrict__ cs,
                          float* __restrict__ out,
                          __half* __restrict__ oh,
                          const float* __restrict__ bias,
                          int Nn, int do_elu) {
    constexpr int HC = H * C;
    int n = (blockIdx.x * blockDim.x + threadIdx.x) >> 5;
    int lane = threadIdx.x & 31;
    if (n >= Nn) return;

    int start = rp[n], end = rp[n + 1];
    float aldv = (lane < H) ? ald[n * H + lane] : 0.f;

    const int col0 = lane * 8;
    const bool act = col0 < HC;
    const int alane = act ? (col0 / C) : 0;
    float acc[8];
#pragma unroll
    for (int i = 0; i < 8; i++) acc[i] = 0.f;
    float sacc = 0.f;

#pragma unroll 4
    for (int k = start; k < end; k++) {
        int src = cs[k];
        float e = 0.f;
        if (lane < H) {
            float v = als[src * H + lane] + aldv;
            v = v > 0.f ? v : 0.2f * v;
            e = __expf(v);
            sacc += e;
        }
        float a = __shfl_sync(0xffffffffu, e, alane);
        if (act) {
            uint4 vv = *(const uint4*)(x + (size_t)src * HC + col0);
            float2 f0 = __half22float2(*(__half2*)&vv.x);
            float2 f1 = __half22float2(*(__half2*)&vv.y);
            float2 f2 = __half22float2(*(__half2*)&vv.z);
            float2 f3 = __half22float2(*(__half2*)&vv.w);
            acc[0] += f0.x * a; acc[1] += f0.y * a;
            acc[2] += f1.x * a; acc[3] += f1.y * a;
            acc[4] += f2.x * a; acc[5] += f2.y * a;
            acc[6] += f3.x * a; acc[7] += f3.y * a;
        }
    }

    float inv_s = (lane < H && sacc > 0.f) ? __frcp_rn(sacc) : 0.f;
    float scale = __shfl_sync(0xffffffffu, inv_s, alane);

    if (act) {
        float o[8];
#pragma unroll
        for (int i = 0; i < 8; i++) {
            float v = acc[i] * scale + bias[col0 + i];
            if (do_elu) v = v > 0.f ? v : expm1f(v);
            o[i] = v;
        }
        if (OUTMODE == 0) {
            float* od = out + (size_t)n * HC + col0;
            *(float4*)(od)     = make_float4(o[0], o[1], o[2], o[3]);
            *(float4*)(od + 4) = make_float4(o[4], o[5], o[6], o[7]);
        } else {
            uint4 p;
            __half2 t0 = __floats2half2_rn(o[0], o[1]);
            __half2 t1 = __floats2half2_rn(o[2], o[3]);
            __half2 t2 = __floats2half2_rn(o[4], o[5]);
            __half2 t3 = __floats2half2_rn(o[6], o[7]);
            p.x = *(uint32_t*)&t0; p.y = *(uint32_t*)&t1;
            p.z = *(uint32_t*)&t2; p.w = *(uint32_t*)&t3;
            *(uint4*)(oh + (size_t)n * HC + col0) = p;
        }
    }
}

// ---------------- launcher (single stream — graph-capture friendly) ---------
extern "C" void kernel_launch(void* const* d_in, const int* in_sizes, int n_in,
                              void* d_out, int out_size) {
    const float* feats = (const float*)d_in[0];
    const void*  ei    = d_in[1];
    const float* W0  = (const float*)d_in[2];
    const float* as0 = (const float*)d_in[3];
    const float* ad0 = (const float*)d_in[4];
    const float* b0  = (const float*)d_in[5];
    const float* W1  = (const float*)d_in[6];
    const float* as1 = (const float*)d_in[7];
    const float* ad1 = (const float*)d_in[8];
    const float* b1  = (const float*)d_in[9];
    const float* W2  = (const float*)d_in[10];
    const float* as2 = (const float*)d_in[11];
    const float* ad2 = (const float*)d_in[12];
    const float* b2  = (const float*)d_in[13];

    int N  = in_sizes[0] / FIN;
    int NE = in_sizes[1] / 2;
    int ET = NE + N;
    float* out = (float*)d_out;
    (void)n_in; (void)out_size;

    __half *pxh, *pa16, *pwt;
    float *pals, *pald;
    int *pdeg, *prp, *pcur, *pcs, *pbs;
    cudaGetSymbolAddress((void**)&pxh,  g_xh);
    cudaGetSymbolAddress((void**)&pa16, g_a16);
    cudaGetSymbolAddress((void**)&pals, g_als);
    cudaGetSymbolAddress((void**)&pald, g_ald);
    cudaGetSymbolAddress((void**)&pdeg, g_deg);
    cudaGetSymbolAddress((void**)&prp,  g_rp);
    cudaGetSymbolAddress((void**)&pcur, g_cur);
    cudaGetSymbolAddress((void**)&pcs,  g_csrc);
    cudaGetSymbolAddress((void**)&pbs,  g_bs);
    cudaGetSymbolAddress((void**)&pwt,  g_wt);

    cudaFuncSetAttribute(gemm_mma, cudaFuncAttributeMaxDynamicSharedMemorySize, SM_GEMM);

    int ethreads = (ET + 255) / 256;
    int nwarps_b = (N * 32 + 255) / 256;
    dim3 grid256(4, (N + BM - 1) / BM);
    dim3 grid40(1, (N + BM - 1) / BM);

    // (1) dtype detect + zero(deg)
    detect_zero_k<<<256, 256>>>((const unsigned int*)ei, pdeg, N + 1);
    // (2) layer-0 weights
    wt_k<<<(256 * 128 + 255) / 256, 256>>>(W0, pwt + 0 * 65536, 128, 256);
    // (3) layer-0 A convert
    asplit_k<<<(N * 128 / 4 + 255) / 256, 256>>>(feats, pa16, N * 128 / 4);
    // (4) layer-0 GEMM  <-- profiled launch
    gemm_mma<<<grid256, 256, SM_GEMM>>>(pa16, pwt, pxh, pals, pald,
                                        as0, ad0, N, 128, 256, 1);

    // --- CSR build (must complete before agg0) ---
    decode_count_k<<<ethreads, 256>>>(ei, NE, N);
    int nb1 = (N + 1023) / 1024;
    scan1_k<<<nb1, 1024>>>(pdeg, prp, pbs, N);
    scan2_k<<<1, 256>>>(pbs, nb1);
    scan3_k<<<(N + 255) / 256, 256>>>(prp, pbs, pcur, N, ET);
    fill_k<<<ethreads, 256>>>(ET);

    // --- layer 0 aggregation (writes fp16 A for layer 1) ---
    gat_agg_h<8, 32, 1><<<nwarps_b, 256>>>(pxh, pals, pald, prp, pcs,
                                           nullptr, pa16, b0, N, 1);

    // --- layer 1: 256 -> 8x32 ---
    wt_k<<<(256 * 256 + 255) / 256, 256>>>(W1, pwt + 1 * 65536, 256, 256);
    gemm_mma<<<grid256, 256, SM_GEMM>>>(pa16, pwt + 65536, pxh,
                                        pals, pald, as1, ad1, N, 256, 256, 1);
    gat_agg_h<8, 32, 1><<<nwarps_b, 256>>>(pxh, pals, pald, prp, pcs,
                                           nullptr, pa16, b1, N, 1);

    // --- layer 2: 256 -> 1x40 ---
    wt_k<<<(40 * 256 + 255) / 256, 256>>>(W2, pwt + 2 * 65536, 256, 40);
    gemm_mma<<<grid40, 256, SM_GEMM>>>(pa16, pwt + 2 * 65536,
                                       pxh, pals, pald, as2, ad2, N, 256, 40, 0);
    compute_al2_h<<<nwarps_b, 256>>>(pxh, as2, ad2, pals, pald, N);
    gat_agg_h<1, 40, 0><<<nwarps_b, 256>>>(pxh, pals, pald, prp, pcs,
                                           out, nullptr, b2, N, 0);
}

// round 12
// speedup vs baseline: 1.2867x; 1.0155x over previous
#include <cuda_runtime.h>
#include <cuda_bf16.h>
#include <cuda_fp16.h>
#include <cstdint>

#define FIN     128
#define NNODES  100000
#define NEDGE   1600000
#define ETOTMAX (NEDGE + NNODES)

#define BM 256
#define BN 64
#define BK 32
#define BKP 40            // padded SMEM row length (fp16 elems) = 80 bytes
#define A_STG 20480       // 256 rows x 80 B
#define B_STG 5120        // 64 rows x 80 B
#define STG_BYTES (A_STG + B_STG)
#define SM_GEMM (2 * STG_BYTES)

// ---------------- scratch (static device globals; no runtime allocation) ----
__device__ __half g_xh[(size_t)NNODES * 256];   // GEMM output (fp16)
__device__ __half g_a16[(size_t)NNODES * 256];  // GEMM A operand (fp16)
__device__ float g_als[NNODES * 8];
__device__ float g_ald[NNODES * 8];
__device__ int   g_src[ETOTMAX];
__device__ int   g_dst[ETOTMAX];
__device__ int   g_deg[NNODES + 1];
__device__ int   g_rp[NNODES + 1];
__device__ int   g_cur[NNODES];
__device__ int   g_csrc[ETOTMAX];
__device__ int   g_bs[256];
__device__ int   g_is64;
__device__ __half g_wt[3][256 * 256];           // per-layer weight (fp16, [N,K])

// ======================= small PTX helpers ==================================
__device__ __forceinline__ uint32_t smem_to_u32(const void* p) {
    uint32_t a;
    asm("{ .reg .u64 t; cvta.to.shared.u64 t, %1; cvt.u32.u64 %0, t; }"
        : "=r"(a) : "l"(p));
    return a;
}
__device__ __forceinline__ void ldsm4(uint32_t* r, uint32_t addr) {
    asm volatile("ldmatrix.sync.aligned.m8n8.x4.shared.b16 {%0,%1,%2,%3}, [%4];"
                 : "=r"(r[0]), "=r"(r[1]), "=r"(r[2]), "=r"(r[3]) : "r"(addr));
}
__device__ __forceinline__ void mma_fp16(float* c, const uint32_t* a, const uint32_t* b) {
    asm volatile("mma.sync.aligned.m16n8k16.row.col.f32.f16.f16.f32 "
                 "{%0,%1,%2,%3}, {%4,%5,%6,%7}, {%8,%9}, {%0,%1,%2,%3};"
                 : "+f"(c[0]), "+f"(c[1]), "+f"(c[2]), "+f"(c[3])
                 : "r"(a[0]), "r"(a[1]), "r"(a[2]), "r"(a[3]), "r"(b[0]), "r"(b[1]));
}
__device__ __forceinline__ void cp16(uint32_t dst, const void* src, bool valid) {
    int sz = valid ? 16 : 0;
    asm volatile("cp.async.cg.shared.global [%0], [%1], 16, %2;"
                 :: "r"(dst), "l"(src), "r"(sz));
}
#define CP_COMMIT() asm volatile("cp.async.commit_group;" ::: "memory")
#define CP_WAIT(n)  asm volatile("cp.async.wait_group %0;" :: "n"(n) : "memory")

// ------- detect edge dtype (block 0) + zero degree array (all blocks) -------
__global__ void detect_zero_k(const unsigned int* __restrict__ w,
                              int* __restrict__ deg, int n) {
    if (blockIdx.x == 0) {
        __shared__ int flag;
        if (threadIdx.x == 0) flag = 0;
        __syncthreads();
        int local = 0;
        for (int i = threadIdx.x; i < 2048; i += blockDim.x)
            if ((i & 1) && w[i]) local = 1;
        if (local) atomicOr(&flag, 1);
        __syncthreads();
        if (threadIdx.x == 0) g_is64 = flag ? 0 : 1;
    }
    for (int i = blockIdx.x * blockDim.x + threadIdx.x; i < n;
         i += gridDim.x * blockDim.x)
        deg[i] = 0;
}

__global__ void decode_count_k(const void* __restrict__ ei, int ne, int n) {
    int e = blockIdx.x * blockDim.x + threadIdx.x;
    int et = ne + n;
    if (e >= et) return;
    int s, d;
    if (e < ne) {
        if (g_is64) {
            const long long* p = (const long long*)ei;
            s = (int)p[e];
            d = (int)p[(size_t)ne + e];
        } else {
            const int* p = (const int*)ei;
            s = p[e];
            d = p[ne + e];
        }
    } else {
        s = e - ne; d = e - ne;
    }
    g_src[e] = s;
    g_dst[e] = d;
    atomicAdd(&g_deg[d], 1);
}

// ---------------- CSR build --------------------------------------------------
__global__ void scan1_k(const int* __restrict__ deg, int* __restrict__ ex,
                        int* __restrict__ bsums, int n) {
    __shared__ int sh[1024];
    int i = blockIdx.x * 1024 + threadIdx.x;
    int v = (i < n) ? deg[i] : 0;
    sh[threadIdx.x] = v;
    __syncthreads();
    for (int off = 1; off < 1024; off <<= 1) {
        int t = (threadIdx.x >= off) ? sh[threadIdx.x - off] : 0;
        __syncthreads();
        sh[threadIdx.x] += t;
        __syncthreads();
    }
    if (i < n) ex[i] = sh[threadIdx.x] - v;
    if (threadIdx.x == 1023) bsums[blockIdx.x] = sh[1023];
}
__global__ void scan2_k(int* __restrict__ bsums, int nb) {
    __shared__ int sh[256];
    int v = (threadIdx.x < nb) ? bsums[threadIdx.x] : 0;
    sh[threadIdx.x] = v;
    __syncthreads();
    for (int off = 1; off < 256; off <<= 1) {
        int t = (threadIdx.x >= off) ? sh[threadIdx.x - off] : 0;
        __syncthreads();
        sh[threadIdx.x] += t;
        __syncthreads();
    }
    if (threadIdx.x < nb) bsums[threadIdx.x] = sh[threadIdx.x] - v;
}
__global__ void scan3_k(int* __restrict__ rp, const int* __restrict__ bsums,
                        int* __restrict__ cur, int n, int total) {
    int i = blockIdx.x * blockDim.x + threadIdx.x;
    if (i < n) {
        rp[i] += bsums[i >> 10];
        cur[i] = 0;
    }
    if (i == 0) rp[n] = total;
}
__global__ void fill_k(int et) {
    int e = blockIdx.x * blockDim.x + threadIdx.x;
    if (e >= et) return;
    int d = g_dst[e];
    int slot = g_rp[d] + atomicAdd(&g_cur[d], 1);
    g_csrc[slot] = g_src[e];
}

// ---------------- W transpose -> fp16 [N,K] ----------------------------------
__global__ void wt_k(const float* __restrict__ W, __half* __restrict__ o,
                     int K, int NT) {
    int idx = blockIdx.x * blockDim.x + threadIdx.x;
    if (idx >= K * NT) return;
    int n = idx / K, k = idx - n * K;
    o[idx] = __float2half_rn(W[(size_t)k * NT + n]);
}

// ---------------- A convert: fp32 -> fp16 (layer 0 input only) --------------
__global__ void asplit_k(const float* __restrict__ A, __half* __restrict__ o,
                         int total4) {
    int i = blockIdx.x * blockDim.x + threadIdx.x;
    if (i >= total4) return;
    float4 v = reinterpret_cast<const float4*>(A)[i];
    uint2 p;
    __half2 t0 = __floats2half2_rn(v.x, v.y);
    __half2 t1 = __floats2half2_rn(v.z, v.w);
    p.x = *reinterpret_cast<uint32_t*>(&t0);
    p.y = *reinterpret_cast<uint32_t*>(&t1);
    reinterpret_cast<uint2*>(o)[i] = p;
}

// ---------------- HMMA fp16 GEMM (BM=256, warp 32x64, cp.async) --------------
// SMEM stage layout (BKP=40 fp16 padded rows):
//   [0, 20480)       A  256 x 32
//   [20480, 25600)   B   64 x 32
__device__ __forceinline__ void stage_cp(
    const __half* __restrict__ A, const __half* __restrict__ B,
    uint32_t sbase, int ctaM, int ctaN, int kc, int M, int NT, int Kdim, int t) {
    // A: 256 rows x 4 cp16 each; thread t handles row t, 4 chunks
    {
        int r = t;
        int row = ctaM + r;
        bool ok = row < M;
        const __half* p = A + (size_t)row * Kdim + kc;
        uint32_t d = sbase + (uint32_t)(r * BKP) * 2;
#pragma unroll
        for (int j = 0; j < 4; j++)
            cp16(d + j * 16, p + j * 8, ok);
    }
    // B: 64 rows x 4 cp16; thread t: row t>>2, chunk t&3
    {
        int n = t >> 2, j = t & 3;
        int gn = ctaN + n;
        bool ok = gn < NT;
        const __half* q = B + (size_t)gn * Kdim + kc + j * 8;
        uint32_t d = sbase + A_STG + (uint32_t)(n * BKP + j * 8) * 2;
        cp16(d, q, ok);
    }
}

__global__ __launch_bounds__(256, 2)
void gemm_mma(const __half* __restrict__ A,
              const __half* __restrict__ B,
              __half* __restrict__ C,
              float* __restrict__ als, float* __restrict__ ald,
              const float* __restrict__ a_src, const float* __restrict__ a_dst,
              int M, int Kdim, int NT, int fuse_al) {
    extern __shared__ char smem[];
    const int t = threadIdx.x;
    const int wid = t >> 5, lane = t & 31;
    const int ctaM = blockIdx.y * BM;
    const int ctaN = blockIdx.x * BN;
    const uint32_t sb = smem_to_u32(smem);

    float acc[2][8][4];
#pragma unroll
    for (int i = 0; i < 2; i++)
#pragma unroll
        for (int j = 0; j < 8; j++)
#pragma unroll
            for (int k = 0; k < 4; k++) acc[i][j][k] = 0.f;

    const int nk = Kdim / BK;

    stage_cp(A, B, sb, ctaM, ctaN, 0, M, NT, Kdim, t);
    CP_COMMIT();

    for (int i = 0; i < nk; i++) {
        if (i + 1 < nk) {
            stage_cp(A, B, sb + ((i + 1) & 1) * STG_BYTES,
                     ctaM, ctaN, (i + 1) * BK, M, NT, Kdim, t);
            CP_COMMIT();
            CP_WAIT(1);
        } else {
            CP_WAIT(0);
        }
        __syncthreads();

        const uint32_t sBase = sb + (uint32_t)((i & 1) * STG_BYTES);
#pragma unroll
        for (int kk = 0; kk < 2; kk++) {
            const int kb = kk * 16;
            uint32_t ah[2][4];
#pragma unroll
            for (int mt = 0; mt < 2; mt++) {
                int row_in = wid * 32 + mt * 16 + (lane & 15);
                int koff = kb + ((lane >> 4) << 3);
                uint32_t off = (uint32_t)(row_in * BKP + koff) * 2;
                ldsm4(ah[mt], sBase + off);
            }
            uint32_t bh[8][2];
#pragma unroll
            for (int nt2 = 0; nt2 < 4; nt2++) {
                int n_in = nt2 * 16 + ((lane >> 4) << 3) + (lane & 7);
                int koff = kb + ((lane >> 3) & 1) * 8;
                uint32_t off = (uint32_t)(n_in * BKP + koff) * 2;
                uint32_t r[4];
                ldsm4(r, sBase + A_STG + off);
                bh[nt2 * 2][0] = r[0]; bh[nt2 * 2][1] = r[1];
                bh[nt2 * 2 + 1][0] = r[2]; bh[nt2 * 2 + 1][1] = r[3];
            }
#pragma unroll
            for (int mt = 0; mt < 2; mt++)
#pragma unroll
                for (int nt = 0; nt < 8; nt++)
                    mma_fp16(acc[mt][nt], ah[mt], bh[nt]);
        }
        __syncthreads();
    }

    // ---- epilogue: write C (fp16) + fused attention logits ----
    // Warp covers 32 rows x 64 cols = 2 heads (C=32).
    const int grp = lane >> 2, q = lane & 3;
#pragma unroll
    for (int mt = 0; mt < 2; mt++) {
#pragma unroll
        for (int half = 0; half < 2; half++) {
            int row = ctaM + wid * 32 + mt * 16 + grp + half * 8;
#pragma unroll
            for (int hg = 0; hg < 2; hg++) {
                float as_p = 0.f, ad_p = 0.f;
#pragma unroll
                for (int nt4 = 0; nt4 < 4; nt4++) {
                    int nt = hg * 4 + nt4;
                    int gcol = ctaN + nt * 8 + q * 2;
                    float v0 = acc[mt][nt][half * 2 + 0];
                    float v1 = acc[mt][nt][half * 2 + 1];
                    if (row < M && gcol < NT)
                        *(__half2*)&C[(size_t)row * NT + gcol] = __floats2half2_rn(v0, v1);
                    if (fuse_al) {
                        as_p += v0 * a_src[gcol] + v1 * a_src[gcol + 1];
                        ad_p += v0 * a_dst[gcol] + v1 * a_dst[gcol + 1];
                    }
                }
                if (fuse_al) {
                    as_p += __shfl_xor_sync(0xffffffffu, as_p, 1);
                    as_p += __shfl_xor_sync(0xffffffffu, as_p, 2);
                    ad_p += __shfl_xor_sync(0xffffffffu, ad_p, 1);
                    ad_p += __shfl_xor_sync(0xffffffffu, ad_p, 2);
                    int head = (ctaN + hg * 32) >> 5;
                    if (q == 0 && row < M) {
                        als[(size_t)row * 8 + head] = as_p;
                        ald[(size_t)row * 8 + head] = ad_p;
                    }
                }
            }
        }
    }
}

// ---------------- attention logits for layer 2 (H=1, C=40, fp16 x) ----------
__global__ void compute_al2_h(const __half* __restrict__ x,
                              const float* __restrict__ a_src,
                              const float* __restrict__ a_dst,
                              float* __restrict__ als, float* __restrict__ ald,
                              int Nn) {
    int n = (blockIdx.x * blockDim.x + threadIdx.x) >> 5;
    int lane = threadIdx.x & 31;
    if (n >= Nn) return;
    const __half* xp = x + (size_t)n * 40;
    float vs = 0.f, vd = 0.f;
    for (int c = lane; c < 40; c += 32) {
        float xv = __half2float(xp[c]);
        vs += xv * a_src[c];
        vd += xv * a_dst[c];
    }
#pragma unroll
    for (int off = 16; off > 0; off >>= 1) {
        vs += __shfl_xor_sync(0xffffffffu, vs, off);
        vd += __shfl_xor_sync(0xffffffffu, vd, off);
    }
    if (lane == 0) { als[n] = vs; ald[n] = vd; }
}

// ------- fused SINGLE-PASS softmax + aggregate + bias(+elu): warp per dst ---
template <int H, int C, int OUTMODE>
__global__ void gat_agg_h(const __half* __restrict__ x,
                          const float* __restrict__ als,
                          const float* __restrict__ ald,
                          const int* __restrict__ rp,
                          const int* __restrict__ cs,
                          float* __restrict__ out,
                          __half* __restrict__ oh,
                          const float* __restrict__ bias,
                          int Nn, int do_elu) {
    constexpr int HC = H * C;
    int n = (blockIdx.x * blockDim.x + threadIdx.x) >> 5;
    int lane = threadIdx.x & 31;
    if (n >= Nn) return;

    int start = rp[n], end = rp[n + 1];
    float aldv = (lane < H) ? ald[n * H + lane] : 0.f;

    const int col0 = lane * 8;
    const bool act = col0 < HC;
    const int alane = act ? (col0 / C) : 0;
    float acc[8];
#pragma unroll
    for (int i = 0; i < 8; i++) acc[i] = 0.f;
    float sacc = 0.f;

#pragma unroll 4
    for (int k = start; k < end; k++) {
        int src = cs[k];
        float e = 0.f;
        if (lane < H) {
            float v = als[src * H + lane] + aldv;
            v = v > 0.f ? v : 0.2f * v;
            e = __expf(v);
            sacc += e;
        }
        float a = __shfl_sync(0xffffffffu, e, alane);
        if (act) {
            uint4 vv = *(const uint4*)(x + (size_t)src * HC + col0);
            float2 f0 = __half22float2(*(__half2*)&vv.x);
            float2 f1 = __half22float2(*(__half2*)&vv.y);
            float2 f2 = __half22float2(*(__half2*)&vv.z);
            float2 f3 = __half22float2(*(__half2*)&vv.w);
            acc[0] += f0.x * a; acc[1] += f0.y * a;
            acc[2] += f1.x * a; acc[3] += f1.y * a;
            acc[4] += f2.x * a; acc[5] += f2.y * a;
            acc[6] += f3.x * a; acc[7] += f3.y * a;
        }
    }

    float inv_s = (lane < H && sacc > 0.f) ? __frcp_rn(sacc) : 0.f;
    float scale = __shfl_sync(0xffffffffu, inv_s, alane);

    if (act) {
        float o[8];
#pragma unroll
        for (int i = 0; i < 8; i++) {
            float v = acc[i] * scale + bias[col0 + i];
            if (do_elu) v = v > 0.f ? v : expm1f(v);
            o[i] = v;
        }
        if (OUTMODE == 0) {
            float* od = out + (size_t)n * HC + col0;
            *(float4*)(od)     = make_float4(o[0], o[1], o[2], o[3]);
            *(float4*)(od + 4) = make_float4(o[4], o[5], o[6], o[7]);
        } else {
            uint4 p;
            __half2 t0 = __floats2half2_rn(o[0], o[1]);
            __half2 t1 = __floats2half2_rn(o[2], o[3]);
            __half2 t2 = __floats2half2_rn(o[4], o[5]);
            __half2 t3 = __floats2half2_rn(o[6], o[7]);
            p.x = *(uint32_t*)&t0; p.y = *(uint32_t*)&t1;
            p.z = *(uint32_t*)&t2; p.w = *(uint32_t*)&t3;
            *(uint4*)(oh + (size_t)n * HC + col0) = p;
        }
    }
}

// ---------------- launcher (single stream — graph-capture friendly) ---------
extern "C" void kernel_launch(void* const* d_in, const int* in_sizes, int n_in,
                              void* d_out, int out_size) {
    const float* feats = (const float*)d_in[0];
    const void*  ei    = d_in[1];
    const float* W0  = (const float*)d_in[2];
    const float* as0 = (const float*)d_in[3];
    const float* ad0 = (const float*)d_in[4];
    const float* b0  = (const float*)d_in[5];
    const float* W1  = (const float*)d_in[6];
    const float* as1 = (const float*)d_in[7];
    const float* ad1 = (const float*)d_in[8];
    const float* b1  = (const float*)d_in[9];
    const float* W2  = (const float*)d_in[10];
    const float* as2 = (const float*)d_in[11];
    const float* ad2 = (const float*)d_in[12];
    const float* b2  = (const float*)d_in[13];

    int N  = in_sizes[0] / FIN;
    int NE = in_sizes[1] / 2;
    int ET = NE + N;
    float* out = (float*)d_out;
    (void)n_in; (void)out_size;

    __half *pxh, *pa16, *pwt;
    float *pals, *pald;
    int *pdeg, *prp, *pcur, *pcs, *pbs;
    cudaGetSymbolAddress((void**)&pxh,  g_xh);
    cudaGetSymbolAddress((void**)&pa16, g_a16);
    cudaGetSymbolAddress((void**)&pals, g_als);
    cudaGetSymbolAddress((void**)&pald, g_ald);
    cudaGetSymbolAddress((void**)&pdeg, g_deg);
    cudaGetSymbolAddress((void**)&prp,  g_rp);
    cudaGetSymbolAddress((void**)&pcur, g_cur);
    cudaGetSymbolAddress((void**)&pcs,  g_csrc);
    cudaGetSymbolAddress((void**)&pbs,  g_bs);
    cudaGetSymbolAddress((void**)&pwt,  g_wt);

    cudaFuncSetAttribute(gemm_mma, cudaFuncAttributeMaxDynamicSharedMemorySize, SM_GEMM);

    int ethreads = (ET + 255) / 256;
    int nwarps_b = (N * 32 + 255) / 256;
    dim3 grid256(4, (N + BM - 1) / BM);
    dim3 grid40(1, (N + BM - 1) / BM);

    // (1) dtype detect + zero(deg)
    detect_zero_k<<<256, 256>>>((const unsigned int*)ei, pdeg, N + 1);
    // (2) layer-0 weights
    wt_k<<<(256 * 128 + 255) / 256, 256>>>(W0, pwt + 0 * 65536, 128, 256);
    // (3) layer-0 A convert
    asplit_k<<<(N * 128 / 4 + 255) / 256, 256>>>(feats, pa16, N * 128 / 4);
    // (4) layer-0 GEMM  <-- profiled launch
    gemm_mma<<<grid256, 256, SM_GEMM>>>(pa16, pwt, pxh, pals, pald,
                                        as0, ad0, N, 128, 256, 1);

    // --- CSR build (must complete before agg0) ---
    decode_count_k<<<ethreads, 256>>>(ei, NE, N);
    int nb1 = (N + 1023) / 1024;
    scan1_k<<<nb1, 1024>>>(pdeg, prp, pbs, N);
    scan2_k<<<1, 256>>>(pbs, nb1);
    scan3_k<<<(N + 255) / 256, 256>>>(prp, pbs, pcur, N, ET);
    fill_k<<<ethreads, 256>>>(ET);

    // --- layer 0 aggregation (writes fp16 A for layer 1) ---
    gat_agg_h<8, 32, 1><<<nwarps_b, 256>>>(pxh, pals, pald, prp, pcs,
                                           nullptr, pa16, b0, N, 1);

    // --- layer 1: 256 -> 8x32 ---
    wt_k<<<(256 * 256 + 255) / 256, 256>>>(W1, pwt + 1 * 65536, 256, 256);
    gemm_mma<<<grid256, 256, SM_GEMM>>>(pa16, pwt + 65536, pxh,
                                        pals, pald, as1, ad1, N, 256, 256, 1);
    gat_agg_h<8, 32, 1><<<nwarps_b, 256>>>(pxh, pals, pald, prp, pcs,
                                           nullptr, pa16, b1, N, 1);

    // --- layer 2: 256 -> 1x40 ---
    wt_k<<<(40 * 256 + 255) / 256, 256>>>(W2, pwt + 2 * 65536, 256, 40);
    gemm_mma<<<grid40, 256, SM_GEMM>>>(pa16, pwt + 2 * 65536,
                                       pxh, pals, pald, as2, ad2, N, 256, 40, 0);
    compute_al2_h<<<nwarps_b, 256>>>(pxh, as2, ad2, pals, pald, N);
    gat_agg_h<1, 40, 0><<<nwarps_b, 256>>>(pxh, pals, pald, prp, pcs,
                                           out, nullptr, b2, N, 0);
}

// round 13
// speedup vs baseline: 1.3744x; 1.0682x over previous
#include <cuda_runtime.h>
#include <cuda_bf16.h>
#include <cuda_fp16.h>
#include <cstdint>

#define FIN     128
#define NNODES  100000
#define NEDGE   1600000
#define ETOTMAX (NEDGE + NNODES)

#define BM 256
#define BN 64
#define BK 32
#define BKP 40            // padded SMEM row length (fp16 elems) = 80 bytes
#define A_STG 20480       // 256 rows x 80 B
#define B_STG 5120        // 64 rows x 80 B
#define STG_BYTES (A_STG + B_STG)
#define NSTAGE 3
#define SM_GEMM (NSTAGE * STG_BYTES)

// ---------------- scratch (static device globals; no runtime allocation) ----
__device__ __half g_xh[(size_t)NNODES * 256];   // GEMM output (fp16)
__device__ __half g_a16[(size_t)NNODES * 256];  // GEMM A operand (fp16)
__device__ float g_als[NNODES * 8];
__device__ float g_ald[NNODES * 8];
__device__ int   g_src[ETOTMAX];
__device__ int   g_dst[ETOTMAX];
__device__ int   g_deg[NNODES + 1];
__device__ int   g_rp[NNODES + 1];
__device__ int   g_cur[NNODES];
__device__ int   g_csrc[ETOTMAX];
__device__ int   g_bs[256];
__device__ int   g_is64;
__device__ __half g_wt[3][256 * 256];           // per-layer weight (fp16, [N,K])

// ======================= small PTX helpers ==================================
__device__ __forceinline__ uint32_t smem_to_u32(const void* p) {
    uint32_t a;
    asm("{ .reg .u64 t; cvta.to.shared.u64 t, %1; cvt.u32.u64 %0, t; }"
        : "=r"(a) : "l"(p));
    return a;
}
__device__ __forceinline__ void ldsm4(uint32_t* r, uint32_t addr) {
    asm volatile("ldmatrix.sync.aligned.m8n8.x4.shared.b16 {%0,%1,%2,%3}, [%4];"
                 : "=r"(r[0]), "=r"(r[1]), "=r"(r[2]), "=r"(r[3]) : "r"(addr));
}
__device__ __forceinline__ void mma_fp16(float* c, const uint32_t* a, const uint32_t* b) {
    asm volatile("mma.sync.aligned.m16n8k16.row.col.f32.f16.f16.f32 "
                 "{%0,%1,%2,%3}, {%4,%5,%6,%7}, {%8,%9}, {%0,%1,%2,%3};"
                 : "+f"(c[0]), "+f"(c[1]), "+f"(c[2]), "+f"(c[3])
                 : "r"(a[0]), "r"(a[1]), "r"(a[2]), "r"(a[3]), "r"(b[0]), "r"(b[1]));
}
__device__ __forceinline__ void cp16(uint32_t dst, const void* src, bool valid) {
    int sz = valid ? 16 : 0;
    asm volatile("cp.async.cg.shared.global [%0], [%1], 16, %2;"
                 :: "r"(dst), "l"(src), "r"(sz));
}
#define CP_COMMIT() asm volatile("cp.async.commit_group;" ::: "memory")
#define CP_WAIT(n)  asm volatile("cp.async.wait_group %0;" :: "n"(n) : "memory")

// ------- detect edge dtype (block 0) + zero degree array (all blocks) -------
__global__ void detect_zero_k(const unsigned int* __restrict__ w,
                              int* __restrict__ deg, int n) {
    if (blockIdx.x == 0) {
        __shared__ int flag;
        if (threadIdx.x == 0) flag = 0;
        __syncthreads();
        int local = 0;
        for (int i = threadIdx.x; i < 2048; i += blockDim.x)
            if ((i & 1) && w[i]) local = 1;
        if (local) atomicOr(&flag, 1);
        __syncthreads();
        if (threadIdx.x == 0) g_is64 = flag ? 0 : 1;
    }
    for (int i = blockIdx.x * blockDim.x + threadIdx.x; i < n;
         i += gridDim.x * blockDim.x)
        deg[i] = 0;
}

__global__ void decode_count_k(const void* __restrict__ ei, int ne, int n) {
    int e = blockIdx.x * blockDim.x + threadIdx.x;
    int et = ne + n;
    if (e >= et) return;
    int s, d;
    if (e < ne) {
        if (g_is64) {
            const long long* p = (const long long*)ei;
            s = (int)p[e];
            d = (int)p[(size_t)ne + e];
        } else {
            const int* p = (const int*)ei;
            s = p[e];
            d = p[ne + e];
        }
    } else {
        s = e - ne; d = e - ne;
    }
    g_src[e] = s;
    g_dst[e] = d;
    atomicAdd(&g_deg[d], 1);
}

// ---------------- CSR build --------------------------------------------------
__global__ void scan1_k(const int* __restrict__ deg, int* __restrict__ ex,
                        int* __restrict__ bsums, int n) {
    __shared__ int sh[1024];
    int i = blockIdx.x * 1024 + threadIdx.x;
    int v = (i < n) ? deg[i] : 0;
    sh[threadIdx.x] = v;
    __syncthreads();
    for (int off = 1; off < 1024; off <<= 1) {
        int t = (threadIdx.x >= off) ? sh[threadIdx.x - off] : 0;
        __syncthreads();
        sh[threadIdx.x] += t;
        __syncthreads();
    }
    if (i < n) ex[i] = sh[threadIdx.x] - v;
    if (threadIdx.x == 1023) bsums[blockIdx.x] = sh[1023];
}
__global__ void scan2_k(int* __restrict__ bsums, int nb) {
    __shared__ int sh[256];
    int v = (threadIdx.x < nb) ? bsums[threadIdx.x] : 0;
    sh[threadIdx.x] = v;
    __syncthreads();
    for (int off = 1; off < 256; off <<= 1) {
        int t = (threadIdx.x >= off) ? sh[threadIdx.x - off] : 0;
        __syncthreads();
        sh[threadIdx.x] += t;
        __syncthreads();
    }
    if (threadIdx.x < nb) bsums[threadIdx.x] = sh[threadIdx.x] - v;
}
__global__ void scan3_k(int* __restrict__ rp, const int* __restrict__ bsums,
                        int* __restrict__ cur, int n, int total) {
    int i = blockIdx.x * blockDim.x + threadIdx.x;
    if (i < n) {
        rp[i] += bsums[i >> 10];
        cur[i] = 0;
    }
    if (i == 0) rp[n] = total;
}
__global__ void fill_k(int et) {
    int e = blockIdx.x * blockDim.x + threadIdx.x;
    if (e >= et) return;
    int d = g_dst[e];
    int slot = g_rp[d] + atomicAdd(&g_cur[d], 1);
    g_csrc[slot] = g_src[e];
}

// ---------------- W transpose -> fp16 [N,K] ----------------------------------
__global__ void wt_k(const float* __restrict__ W, __half* __restrict__ o,
                     int K, int NT) {
    int idx = blockIdx.x * blockDim.x + threadIdx.x;
    if (idx >= K * NT) return;
    int n = idx / K, k = idx - n * K;
    o[idx] = __float2half_rn(W[(size_t)k * NT + n]);
}

// ---------------- A convert: fp32 -> fp16 (layer 0 input only) --------------
__global__ void asplit_k(const float* __restrict__ A, __half* __restrict__ o,
                         int total4) {
    int i = blockIdx.x * blockDim.x + threadIdx.x;
    if (i >= total4) return;
    float4 v = reinterpret_cast<const float4*>(A)[i];
    uint2 p;
    __half2 t0 = __floats2half2_rn(v.x, v.y);
    __half2 t1 = __floats2half2_rn(v.z, v.w);
    p.x = *reinterpret_cast<uint32_t*>(&t0);
    p.y = *reinterpret_cast<uint32_t*>(&t1);
    reinterpret_cast<uint2*>(o)[i] = p;
}

// ---------------- HMMA fp16 GEMM (BM=256, warp 32x64, 3-stage cp.async) ------
__device__ __forceinline__ void stage_cp(
    const __half* __restrict__ A, const __half* __restrict__ B,
    uint32_t sbase, int ctaM, int ctaN, int kc, int M, int NT, int Kdim, int t) {
    {
        int r = t;
        int row = ctaM + r;
        bool ok = row < M;
        const __half* p = A + (size_t)row * Kdim + kc;
        uint32_t d = sbase + (uint32_t)(r * BKP) * 2;
#pragma unroll
        for (int j = 0; j < 4; j++)
            cp16(d + j * 16, p + j * 8, ok);
    }
    {
        int n = t >> 2, j = t & 3;
        int gn = ctaN + n;
        bool ok = gn < NT;
        const __half* q = B + (size_t)gn * Kdim + kc + j * 8;
        uint32_t d = sbase + A_STG + (uint32_t)(n * BKP + j * 8) * 2;
        cp16(d, q, ok);
    }
}

__global__ __launch_bounds__(256, 2)
void gemm_mma(const __half* __restrict__ A,
              const __half* __restrict__ B,
              __half* __restrict__ C,
              float* __restrict__ als, float* __restrict__ ald,
              const float* __restrict__ a_src, const float* __restrict__ a_dst,
              int M, int Kdim, int NT, int fuse_al) {
    extern __shared__ char smem[];
    const int t = threadIdx.x;
    const int wid = t >> 5, lane = t & 31;
    const int ctaM = blockIdx.y * BM;
    const int ctaN = blockIdx.x * BN;
    const uint32_t sb = smem_to_u32(smem);

    float acc[2][8][4];
#pragma unroll
    for (int i = 0; i < 2; i++)
#pragma unroll
        for (int j = 0; j < 8; j++)
#pragma unroll
            for (int k = 0; k < 4; k++) acc[i][j][k] = 0.f;

    const int nk = Kdim / BK;

    // 3-stage pipeline prologue: issue stages 0 and 1
    stage_cp(A, B, sb, ctaM, ctaN, 0, M, NT, Kdim, t);
    CP_COMMIT();
    if (nk > 1) {
        stage_cp(A, B, sb + STG_BYTES, ctaM, ctaN, BK, M, NT, Kdim, t);
        CP_COMMIT();
    }

    for (int i = 0; i < nk; i++) {
        // wait for stage i (group i) to complete
        if (i + 1 < nk) { CP_WAIT(1); } else { CP_WAIT(0); }
        __syncthreads();   // data visible to all; all warps done with stage i-1

        // issue stage i+2 into buffer (i+2)%3 (last consumed at iter i-1)
        if (i + 2 < nk) {
            stage_cp(A, B, sb + ((i + 2) % NSTAGE) * STG_BYTES,
                     ctaM, ctaN, (i + 2) * BK, M, NT, Kdim, t);
            CP_COMMIT();
        }

        const uint32_t sBase = sb + (uint32_t)((i % NSTAGE) * STG_BYTES);
#pragma unroll
        for (int kk = 0; kk < 2; kk++) {
            const int kb = kk * 16;
            uint32_t ah[2][4];
#pragma unroll
            for (int mt = 0; mt < 2; mt++) {
                int row_in = wid * 32 + mt * 16 + (lane & 15);
                int koff = kb + ((lane >> 4) << 3);
                uint32_t off = (uint32_t)(row_in * BKP + koff) * 2;
                ldsm4(ah[mt], sBase + off);
            }
            uint32_t bh[8][2];
#pragma unroll
            for (int nt2 = 0; nt2 < 4; nt2++) {
                int n_in = nt2 * 16 + ((lane >> 4) << 3) + (lane & 7);
                int koff = kb + ((lane >> 3) & 1) * 8;
                uint32_t off = (uint32_t)(n_in * BKP + koff) * 2;
                uint32_t r[4];
                ldsm4(r, sBase + A_STG + off);
                bh[nt2 * 2][0] = r[0]; bh[nt2 * 2][1] = r[1];
                bh[nt2 * 2 + 1][0] = r[2]; bh[nt2 * 2 + 1][1] = r[3];
            }
#pragma unroll
            for (int mt = 0; mt < 2; mt++)
#pragma unroll
                for (int nt = 0; nt < 8; nt++)
                    mma_fp16(acc[mt][nt], ah[mt], bh[nt]);
        }
    }

    // ---- epilogue: write C (fp16) + fused attention logits ----
    // fuse_al==1: 2 heads of C=32 per warp.  fuse_al==2: single head over NT cols.
    const int grp = lane >> 2, q = lane & 3;
#pragma unroll
    for (int mt = 0; mt < 2; mt++) {
#pragma unroll
        for (int half = 0; half < 2; half++) {
            int row = ctaM + wid * 32 + mt * 16 + grp + half * 8;
            float as_tot = 0.f, ad_tot = 0.f;
#pragma unroll
            for (int hg = 0; hg < 2; hg++) {
                float as_p = 0.f, ad_p = 0.f;
#pragma unroll
                for (int nt4 = 0; nt4 < 4; nt4++) {
                    int nt = hg * 4 + nt4;
                    int gcol = ctaN + nt * 8 + q * 2;
                    float v0 = acc[mt][nt][half * 2 + 0];
                    float v1 = acc[mt][nt][half * 2 + 1];
                    bool okc = gcol < NT;
                    if (row < M && okc)
                        *(__half2*)&C[(size_t)row * NT + gcol] = __floats2half2_rn(v0, v1);
                    if (fuse_al && okc) {
                        as_p += v0 * a_src[gcol] + v1 * a_src[gcol + 1];
                        ad_p += v0 * a_dst[gcol] + v1 * a_dst[gcol + 1];
                    }
                }
                if (fuse_al == 1) {
                    as_p += __shfl_xor_sync(0xffffffffu, as_p, 1);
                    as_p += __shfl_xor_sync(0xffffffffu, as_p, 2);
                    ad_p += __shfl_xor_sync(0xffffffffu, ad_p, 1);
                    ad_p += __shfl_xor_sync(0xffffffffu, ad_p, 2);
                    int head = (ctaN + hg * 32) >> 5;
                    if (q == 0 && row < M) {
                        als[(size_t)row * 8 + head] = as_p;
                        ald[(size_t)row * 8 + head] = ad_p;
                    }
                } else {
                    as_tot += as_p;
                    ad_tot += ad_p;
                }
            }
            if (fuse_al == 2) {
                as_tot += __shfl_xor_sync(0xffffffffu, as_tot, 1);
                as_tot += __shfl_xor_sync(0xffffffffu, as_tot, 2);
                ad_tot += __shfl_xor_sync(0xffffffffu, ad_tot, 1);
                ad_tot += __shfl_xor_sync(0xffffffffu, ad_tot, 2);
                if (q == 0 && row < M) {
                    als[row] = as_tot;
                    ald[row] = ad_tot;
                }
            }
        }
    }
}

// ------- fused SINGLE-PASS softmax + aggregate + bias(+elu): warp per dst ---
// 2-edge unrolled main loop for memory-level parallelism.
template <int H, int C, int OUTMODE>
__global__ void gat_agg_h(const __half* __restrict__ x,
                          const float* __restrict__ als,
                          const float* __restrict__ ald,
                          const int* __restrict__ rp,
                          const int* __restrict__ cs,
                          float* __restrict__ out,
                          __half* __restrict__ oh,
                          const float* __restrict__ bias,
                          int Nn, int do_elu) {
    constexpr int HC = H * C;
    int n = (blockIdx.x * blockDim.x + threadIdx.x) >> 5;
    int lane = threadIdx.x & 31;
    if (n >= Nn) return;

    int start = rp[n], end = rp[n + 1];
    float aldv = (lane < H) ? ald[n * H + lane] : 0.f;

    const int col0 = lane * 8;
    const bool act = col0 < HC;
    const int alane = act ? (col0 / C) : 0;
    float acc[8];
#pragma unroll
    for (int i = 0; i < 8; i++) acc[i] = 0.f;
    float sacc = 0.f;

    int k = start;
    for (; k + 1 < end; k += 2) {
        int s0 = cs[k], s1 = cs[k + 1];
        float e0 = 0.f, e1 = 0.f;
        if (lane < H) {
            float v0 = als[s0 * H + lane] + aldv;
            float v1 = als[s1 * H + lane] + aldv;
            v0 = v0 > 0.f ? v0 : 0.2f * v0;
            v1 = v1 > 0.f ? v1 : 0.2f * v1;
            e0 = __expf(v0);
            e1 = __expf(v1);
            sacc += e0 + e1;
        }
        float a0 = __shfl_sync(0xffffffffu, e0, alane);
        float a1 = __shfl_sync(0xffffffffu, e1, alane);
        if (act) {
            uint4 w0 = *(const uint4*)(x + (size_t)s0 * HC + col0);
            uint4 w1 = *(const uint4*)(x + (size_t)s1 * HC + col0);
            float2 f;
            f = __half22float2(*(__half2*)&w0.x); acc[0] += f.x * a0; acc[1] += f.y * a0;
            f = __half22float2(*(__half2*)&w0.y); acc[2] += f.x * a0; acc[3] += f.y * a0;
            f = __half22float2(*(__half2*)&w0.z); acc[4] += f.x * a0; acc[5] += f.y * a0;
            f = __half22float2(*(__half2*)&w0.w); acc[6] += f.x * a0; acc[7] += f.y * a0;
            f = __half22float2(*(__half2*)&w1.x); acc[0] += f.x * a1; acc[1] += f.y * a1;
            f = __half22float2(*(__half2*)&w1.y); acc[2] += f.x * a1; acc[3] += f.y * a1;
            f = __half22float2(*(__half2*)&w1.z); acc[4] += f.x * a1; acc[5] += f.y * a1;
            f = __half22float2(*(__half2*)&w1.w); acc[6] += f.x * a1; acc[7] += f.y * a1;
        }
    }
    if (k < end) {
        int s0 = cs[k];
        float e0 = 0.f;
        if (lane < H) {
            float v0 = als[s0 * H + lane] + aldv;
            v0 = v0 > 0.f ? v0 : 0.2f * v0;
            e0 = __expf(v0);
            sacc += e0;
        }
        float a0 = __shfl_sync(0xffffffffu, e0, alane);
        if (act) {
            uint4 w0 = *(const uint4*)(x + (size_t)s0 * HC + col0);
            float2 f;
            f = __half22float2(*(__half2*)&w0.x); acc[0] += f.x * a0; acc[1] += f.y * a0;
            f = __half22float2(*(__half2*)&w0.y); acc[2] += f.x * a0; acc[3] += f.y * a0;
            f = __half22float2(*(__half2*)&w0.z); acc[4] += f.x * a0; acc[5] += f.y * a0;
            f = __half22float2(*(__half2*)&w0.w); acc[6] += f.x * a0; acc[7] += f.y * a0;
        }
    }

    float inv_s = (lane < H && sacc > 0.f) ? __frcp_rn(sacc) : 0.f;
    float scale = __shfl_sync(0xffffffffu, inv_s, alane);

    if (act) {
        float o[8];
#pragma unroll
        for (int i = 0; i < 8; i++) {
            float v = acc[i] * scale + bias[col0 + i];
            if (do_elu) v = v > 0.f ? v : expm1f(v);
            o[i] = v;
        }
        if (OUTMODE == 0) {
            float* od = out + (size_t)n * HC + col0;
            *(float4*)(od)     = make_float4(o[0], o[1], o[2], o[3]);
            *(float4*)(od + 4) = make_float4(o[4], o[5], o[6], o[7]);
        } else {
            uint4 p;
            __half2 t0 = __floats2half2_rn(o[0], o[1]);
            __half2 t1 = __floats2half2_rn(o[2], o[3]);
            __half2 t2 = __floats2half2_rn(o[4], o[5]);
            __half2 t3 = __floats2half2_rn(o[6], o[7]);
            p.x = *(uint32_t*)&t0; p.y = *(uint32_t*)&t1;
            p.z = *(uint32_t*)&t2; p.w = *(uint32_t*)&t3;
            *(uint4*)(oh + (size_t)n * HC + col0) = p;
        }
    }
}

// ---------------- launcher (single stream — graph-capture friendly) ---------
extern "C" void kernel_launch(void* const* d_in, const int* in_sizes, int n_in,
                              void* d_out, int out_size) {
    const float* feats = (const float*)d_in[0];
    const void*  ei    = d_in[1];
    const float* W0  = (const float*)d_in[2];
    const float* as0 = (const float*)d_in[3];
    const float* ad0 = (const float*)d_in[4];
    const float* b0  = (const float*)d_in[5];
    const float* W1  = (const float*)d_in[6];
    const float* as1 = (const float*)d_in[7];
    const float* ad1 = (const float*)d_in[8];
    const float* b1  = (const float*)d_in[9];
    const float* W2  = (const float*)d_in[10];
    const float* as2 = (const float*)d_in[11];
    const float* ad2 = (const float*)d_in[12];
    const float* b2  = (const float*)d_in[13];

    int N  = in_sizes[0] / FIN;
    int NE = in_sizes[1] / 2;
    int ET = NE + N;
    float* out = (float*)d_out;
    (void)n_in; (void)out_size;

    __half *pxh, *pa16, *pwt;
    float *pals, *pald;
    int *pdeg, *prp, *pcur, *pcs, *pbs;
    cudaGetSymbolAddress((void**)&pxh,  g_xh);
    cudaGetSymbolAddress((void**)&pa16, g_a16);
    cudaGetSymbolAddress((void**)&pals, g_als);
    cudaGetSymbolAddress((void**)&pald, g_ald);
    cudaGetSymbolAddress((void**)&pdeg, g_deg);
    cudaGetSymbolAddress((void**)&prp,  g_rp);
    cudaGetSymbolAddress((void**)&pcur, g_cur);
    cudaGetSymbolAddress((void**)&pcs,  g_csrc);
    cudaGetSymbolAddress((void**)&pbs,  g_bs);
    cudaGetSymbolAddress((void**)&pwt,  g_wt);

    cudaFuncSetAttribute(gemm_mma, cudaFuncAttributeMaxDynamicSharedMemorySize, SM_GEMM);

    int ethreads = (ET + 255) / 256;
    int nwarps_b = (N * 32 + 255) / 256;
    dim3 grid256(4, (N + BM - 1) / BM);
    dim3 grid40(1, (N + BM - 1) / BM);

    // (1) dtype detect + zero(deg)
    detect_zero_k<<<256, 256>>>((const unsigned int*)ei, pdeg, N + 1);
    // (2) layer-0 weights
    wt_k<<<(256 * 128 + 255) / 256, 256>>>(W0, pwt + 0 * 65536, 128, 256);
    // (3) layer-0 A convert
    asplit_k<<<(N * 128 / 4 + 255) / 256, 256>>>(feats, pa16, N * 128 / 4);
    // (4) layer-0 GEMM  <-- profiled launch
    gemm_mma<<<grid256, 256, SM_GEMM>>>(pa16, pwt, pxh, pals, pald,
                                        as0, ad0, N, 128, 256, 1);

    // --- CSR build (must complete before agg0) ---
    decode_count_k<<<ethreads, 256>>>(ei, NE, N);
    int nb1 = (N + 1023) / 1024;
    scan1_k<<<nb1, 1024>>>(pdeg, prp, pbs, N);
    scan2_k<<<1, 256>>>(pbs, nb1);
    scan3_k<<<(N + 255) / 256, 256>>>(prp, pbs, pcur, N, ET);
    fill_k<<<ethreads, 256>>>(ET);

    // --- layer 0 aggregation (writes fp16 A for layer 1) ---
    gat_agg_h<8, 32, 1><<<nwarps_b, 256>>>(pxh, pals, pald, prp, pcs,
                                           nullptr, pa16, b0, N, 1);

    // --- layer 1: 256 -> 8x32 ---
    wt_k<<<(256 * 256 + 255) / 256, 256>>>(W1, pwt + 1 * 65536, 256, 256);
    gemm_mma<<<grid256, 256, SM_GEMM>>>(pa16, pwt + 65536, pxh,
                                        pals, pald, as1, ad1, N, 256, 256, 1);
    gat_agg_h<8, 32, 1><<<nwarps_b, 256>>>(pxh, pals, pald, prp, pcs,
                                           nullptr, pa16, b1, N, 1);

    // --- layer 2: 256 -> 1x40 (al fused into GEMM epilogue, mode 2) ---
    wt_k<<<(40 * 256 + 255) / 256, 256>>>(W2, pwt + 2 * 65536, 256, 40);
    gemm_mma<<<grid40, 256, SM_GEMM>>>(pa16, pwt + 2 * 65536,
                                       pxh, pals, pald, as2, ad2, N, 256, 40, 2);
    gat_agg_h<1, 40, 0><<<nwarps_b, 256>>>(pxh, pals, pald, prp, pcs,
                                           out, nullptr, b2, N, 0);
}